// round 1
// baseline (speedup 1.0000x reference)
#include <cuda_runtime.h>
#include <math.h>

#define NB 16
#define LL 1000
#define DD 1024
#define MM (NB*LL)   // 16000

// ---------------- scratch (static device globals; no allocation) ----------------
__device__ float g_x  [NB*LL*DD];
__device__ float g_xu [NB*LL*DD];
__device__ float g_qh [NB*LL*DD];
__device__ float g_kh [NB*LL*DD];
__device__ float g_vh [NB*LL*DD];
__device__ float g_quh[NB*LL*DD];
__device__ float g_s1 [NB*LL*LL];
__device__ float g_s2 [NB*LL*LL];
__device__ float g_o1 [NB*LL*DD];
__device__ float g_o2 [NB*LL*DD];
__device__ float g_yn [NB*LL*DD];

// ---------------- positional encoding + input add ----------------
// pe[l, j] = (j even) ? sin(l * 10000^{-j/1024}) : cos(l * 10000^{-j/1024})
// computed once per (l, j), broadcast over batch.
__global__ void build_x_kernel(const float* __restrict__ inp,
                               const float* __restrict__ inp2)
{
    int idx = blockIdx.x * blockDim.x + threadIdx.x;
    if (idx >= LL * DD) return;
    int l = idx / DD;
    int j = idx % DD;
    // rate = 10000^{-j/1024} = exp(-j * ln(10000)/1024)
    float rate = expf(-(float)j * 8.99447363e-3f);
    float ang  = (float)l * rate;
    float pe   = (j & 1) ? cosf(ang) : sinf(ang);
#pragma unroll
    for (int n = 0; n < NB; n++) {
        long long o = (long long)n * LL * DD + idx;
        g_x [o] = inp [o] + pe;
        g_xu[o] = inp2[o] + pe;
    }
}

// ---------------- tiled fp32 GEMM ----------------
// C[M,Nn] = A[M,K] * op(B)   (BT: B is [Nn,K] row-major -> C = A B^T;
//                            !BT: B is [K,Nn] row-major -> C = A B)
// CSKIP: causal score tiles: skip blocks entirely above the diagonal (M==Nn tiles)
// CKLIM: limit K loop to m0+BM (P has exact zeros above diagonal)
// BIAS : add bias[n]
template<bool BT, bool CSKIP, bool CKLIM, bool BIAS>
__global__ __launch_bounds__(256, 2)
void gemm128(const float* __restrict__ A, const float* __restrict__ B,
             float* __restrict__ C, const float* __restrict__ bias,
             int M, int Nn, int K, int lda, int ldb, int ldc,
             long long sA, long long sB, long long sC)
{
    const int BM = 128, BN = 128, BK = 16;
    __shared__ float As[BK][BM];
    __shared__ float Bs[BK][BN];

    int bz = blockIdx.z;
    A += (long long)bz * sA;
    B += (long long)bz * sB;
    C += (long long)bz * sC;

    int m0 = blockIdx.y * BM;
    int n0 = blockIdx.x * BN;
    if (CSKIP && n0 > m0 + BM - 1) return;

    int tid  = threadIdx.x;
    int trow = tid >> 4;     // 0..15
    int tcol = tid & 15;     // 0..15

    float acc[8][8];
#pragma unroll
    for (int i = 0; i < 8; i++)
#pragma unroll
        for (int j = 0; j < 8; j++) acc[i][j] = 0.f;

    int ktiles = (K + BK - 1) / BK;
    if (CKLIM) {
        int kl = (m0 + BM + BK - 1) / BK;
        if (kl < ktiles) ktiles = kl;
    }

    for (int kt = 0; kt < ktiles; kt++) {
        int k0 = kt * BK;
        // ---- load A tile: 128 rows x 16 k, transposed into As[k][m]
#pragma unroll
        for (int jj = 0; jj < 2; jj++) {
            int i  = tid + jj * 256;       // 0..511
            int r  = i >> 2;               // 0..127
            int c4 = (i & 3) * 4;          // 0,4,8,12
            float4 v = make_float4(0.f, 0.f, 0.f, 0.f);
            int gr = m0 + r;
            if (gr < M && (k0 + c4 + 4) <= K)
                v = *(const float4*)(A + (long long)gr * lda + k0 + c4);
            As[c4 + 0][r] = v.x;
            As[c4 + 1][r] = v.y;
            As[c4 + 2][r] = v.z;
            As[c4 + 3][r] = v.w;
        }
        // ---- load B tile
        if (BT) {
            // B [Nn, K] row-major: rows n0..n0+127, transposed into Bs[k][n]
#pragma unroll
            for (int jj = 0; jj < 2; jj++) {
                int i  = tid + jj * 256;
                int r  = i >> 2;
                int c4 = (i & 3) * 4;
                float4 v = make_float4(0.f, 0.f, 0.f, 0.f);
                int gr = n0 + r;
                if (gr < Nn && (k0 + c4 + 4) <= K)
                    v = *(const float4*)(B + (long long)gr * ldb + k0 + c4);
                Bs[c4 + 0][r] = v.x;
                Bs[c4 + 1][r] = v.y;
                Bs[c4 + 2][r] = v.z;
                Bs[c4 + 3][r] = v.w;
            }
        } else {
            // B [K, Nn] row-major: rows k0..k0+15, direct into Bs[k][n]
#pragma unroll
            for (int jj = 0; jj < 2; jj++) {
                int i  = tid + jj * 256;
                int rk = i >> 5;              // 0..15
                int c4 = (i & 31) * 4;        // 0..124
                float4 v = make_float4(0.f, 0.f, 0.f, 0.f);
                if ((k0 + rk) < K && (n0 + c4 + 4) <= Nn)
                    v = *(const float4*)(B + (long long)(k0 + rk) * ldb + n0 + c4);
                *(float4*)&Bs[rk][c4] = v;
            }
        }
        __syncthreads();

#pragma unroll
        for (int kk = 0; kk < BK; kk++) {
            float a[8], b[8];
            *(float4*)&a[0] = *(const float4*)&As[kk][trow * 8];
            *(float4*)&a[4] = *(const float4*)&As[kk][trow * 8 + 4];
            *(float4*)&b[0] = *(const float4*)&Bs[kk][tcol * 8];
            *(float4*)&b[4] = *(const float4*)&Bs[kk][tcol * 8 + 4];
#pragma unroll
            for (int i = 0; i < 8; i++)
#pragma unroll
                for (int j = 0; j < 8; j++)
                    acc[i][j] += a[i] * b[j];
        }
        __syncthreads();
    }

    // ---- epilogue
#pragma unroll
    for (int i = 0; i < 8; i++) {
        int gm = m0 + trow * 8 + i;
        if (gm >= M) continue;
#pragma unroll
        for (int j = 0; j < 8; j++) {
            int gn = n0 + tcol * 8 + j;
            if (gn >= Nn) continue;
            float v = acc[i][j];
            if (BIAS) v += bias[gn];
            C[(long long)gm * ldc + gn] = v;
        }
    }
}

// ---------------- causal softmax (in-place on S -> P) ----------------
// Row q: softmax over k in [0, q]; writes 0 for k in (q, LL).
__global__ void softmax_causal_kernel(float* __restrict__ S)
{
    int q = blockIdx.x;
    int n = blockIdx.y;
    float* row = S + ((long long)n * LL + q) * (long long)LL;
    int len = q + 1;
    int tid = threadIdx.x;
    __shared__ float red[256];

    float mx = -3.4e38f;
    for (int k = tid; k < len; k += 256) mx = fmaxf(mx, row[k]);
    red[tid] = mx;
    __syncthreads();
    for (int s = 128; s > 0; s >>= 1) {
        if (tid < s) red[tid] = fmaxf(red[tid], red[tid + s]);
        __syncthreads();
    }
    mx = red[0];
    __syncthreads();

    float sum = 0.f;
    for (int k = tid; k < len; k += 256) {
        float e = expf(row[k] - mx);
        row[k] = e;
        sum += e;
    }
    red[tid] = sum;
    __syncthreads();
    for (int s = 128; s > 0; s >>= 1) {
        if (tid < s) red[tid] += red[tid + s];
        __syncthreads();
    }
    float inv = 1.f / red[0];

    for (int k = tid; k < len; k += 256) row[k] *= inv;
    for (int k = len + tid; k < LL; k += 256) row[k] = 0.f;
}

// ---------------- combine + residual + layernorm ----------------
// A == 0.5 exactly (E_c == E_u in the reference), so:
//   y = 0.5*(o1+o2) + inputs ; yn = (y-mu)/sqrt(var+eps)*g + b
__global__ void fuse_ln_kernel(const float* __restrict__ inp,
                               const float* __restrict__ ln_g,
                               const float* __restrict__ ln_b)
{
    int r = blockIdx.x;                     // 0..15999
    long long base = (long long)r * DD;
    const float* o1 = g_o1 + base;
    const float* o2 = g_o2 + base;
    const float* xr = inp  + base;
    float*       yn = g_yn + base;
    int tid = threadIdx.x;

    __shared__ float ssum[256];
    __shared__ float ssq [256];

    float v[4];
    float s = 0.f, s2 = 0.f;
#pragma unroll
    for (int i = 0; i < 4; i++) {
        int d = tid + i * 256;
        float y = 0.5f * (o1[d] + o2[d]) + xr[d];
        v[i] = y;
        s  += y;
        s2 += y * y;
    }
    ssum[tid] = s;
    ssq [tid] = s2;
    __syncthreads();
    for (int st = 128; st > 0; st >>= 1) {
        if (tid < st) { ssum[tid] += ssum[tid + st]; ssq[tid] += ssq[tid + st]; }
        __syncthreads();
    }
    float mu  = ssum[0] * (1.f / DD);
    float var = ssq[0]  * (1.f / DD) - mu * mu;
    float inv = rsqrtf(var + 1e-5f);
#pragma unroll
    for (int i = 0; i < 4; i++) {
        int d = tid + i * 256;
        yn[d] = (v[i] - mu) * inv * ln_g[d] + ln_b[d];
    }
}

// ---------------- host launch ----------------
extern "C" void kernel_launch(void* const* d_in, const int* in_sizes, int n_in,
                              void* d_out, int out_size)
{
    const float* inputs  = (const float*)d_in[0];
    const float* inputs2 = (const float*)d_in[1];
    const float* Wq      = (const float*)d_in[2];
    const float* Wqu     = (const float*)d_in[3];
    const float* Wk      = (const float*)d_in[4];
    const float* Wv      = (const float*)d_in[5];
    // d_in[6] W_d, d_in[7] h_vec: dead code (A == 0.5 exactly)
    const float* fc_w    = (const float*)d_in[8];
    const float* fc_b    = (const float*)d_in[9];
    const float* ln_g    = (const float*)d_in[10];
    const float* ln_b    = (const float*)d_in[11];
    float* out = (float*)d_out;

    float *x, *xu, *qh, *kh, *vh, *quh, *s1, *s2, *o1, *o2, *yn;
    cudaGetSymbolAddress((void**)&x,   g_x);
    cudaGetSymbolAddress((void**)&xu,  g_xu);
    cudaGetSymbolAddress((void**)&qh,  g_qh);
    cudaGetSymbolAddress((void**)&kh,  g_kh);
    cudaGetSymbolAddress((void**)&vh,  g_vh);
    cudaGetSymbolAddress((void**)&quh, g_quh);
    cudaGetSymbolAddress((void**)&s1,  g_s1);
    cudaGetSymbolAddress((void**)&s2,  g_s2);
    cudaGetSymbolAddress((void**)&o1,  g_o1);
    cudaGetSymbolAddress((void**)&o2,  g_o2);
    cudaGetSymbolAddress((void**)&yn,  g_yn);

    // 1. x = inputs + pe, xu = inputs2 + pe
    build_x_kernel<<<(LL * DD + 255) / 256, 256>>>(inputs, inputs2);

    // 2. projections: [16000,1024] @ [1024,1024]^T
    dim3 gproj(DD / 128, MM / 128);   // (8, 125)
    gemm128<true, false, false, false><<<gproj, 256>>>(x,  Wq,  qh,  nullptr, MM, DD, DD, DD, DD, DD, 0, 0, 0);
    gemm128<true, false, false, false><<<gproj, 256>>>(x,  Wk,  kh,  nullptr, MM, DD, DD, DD, DD, DD, 0, 0, 0);
    gemm128<true, false, false, false><<<gproj, 256>>>(x,  Wv,  vh,  nullptr, MM, DD, DD, DD, DD, DD, 0, 0, 0);
    gemm128<true, false, false, false><<<gproj, 256>>>(xu, Wqu, quh, nullptr, MM, DD, DD, DD, DD, DD, 0, 0, 0);

    // 3. scores (causal tile skip): S = Q @ K^T per batch
    dim3 gsc(8, 8, NB);
    long long sQK = (long long)LL * DD, sS = (long long)LL * LL;
    gemm128<true, true, false, false><<<gsc, 256>>>(qh,  kh, s1, nullptr, LL, LL, DD, DD, DD, LL, sQK, sQK, sS);
    gemm128<true, true, false, false><<<gsc, 256>>>(quh, kh, s2, nullptr, LL, LL, DD, DD, DD, LL, sQK, sQK, sS);

    // 4. causal softmax in place (S -> P, zeros above diagonal)
    dim3 gsm(LL, NB);
    softmax_causal_kernel<<<gsm, 256>>>(s1);
    softmax_causal_kernel<<<gsm, 256>>>(s2);

    // 5. O = P @ V per batch (K loop capped at block's max query)
    dim3 go(DD / 128, 8, NB);
    gemm128<false, false, true, false><<<go, 256>>>(s1, vh, o1, nullptr, LL, DD, LL, LL, DD, DD, sS, sQK, sQK);
    gemm128<false, false, true, false><<<go, 256>>>(s2, vh, o2, nullptr, LL, DD, LL, LL, DD, DD, sS, sQK, sQK);

    // 6. y = 0.5*(o1+o2) + inputs; layernorm -> yn
    fuse_ln_kernel<<<MM, 256>>>(inputs, ln_g, ln_b);

    // 7. out = yn @ fc_w^T + fc_b
    gemm128<true, false, false, true><<<gproj, 256>>>(yn, fc_w, out, fc_b, MM, DD, DD, DD, DD, DD, 0, 0, 0);
}

// round 3
// speedup vs baseline: 1.7491x; 1.7491x over previous
#include <cuda_runtime.h>
#include <cstdint>
#include <math.h>

#define NB 16
#define LL 1000
#define DD 1024
#define MM (NB*LL)   // 16000

// Arch-feature gate: defined only when compiling for compute_103a/compute_100a,
// which is required for tcgen05. The plain compute_103 pass compiles the
// FFMA fallback instead; host launches both (one is always an empty no-op).
#if defined(__CUDA_ARCH__) && (defined(__CUDA_ARCH_FEAT_SM103_ALL) || defined(__CUDA_ARCH_FEAT_SM100_ALL))
#define TC_OK 1
#endif

// ---------------- scratch (static device globals; no allocation) ----------------
__device__ float g_x  [NB*LL*DD];
__device__ float g_xu [NB*LL*DD];
__device__ float g_qh [NB*LL*DD];
__device__ float g_kh [NB*LL*DD];
__device__ float g_vt [NB*DD*LL];   // V transposed: [batch][1024][1000]
__device__ float g_quh[NB*LL*DD];
__device__ float g_s1 [NB*LL*LL];
__device__ float g_s2 [NB*LL*LL];
__device__ float g_o1 [NB*LL*DD];
__device__ float g_o2 [NB*LL*DD];
__device__ float g_yn [NB*LL*DD];

// ================= PTX helpers =================
__device__ __forceinline__ uint32_t smem_u32(const void* p) {
    uint32_t a;
    asm("{ .reg .u64 t; cvta.to.shared.u64 t, %1; cvt.u32.u64 %0, t; }" : "=r"(a) : "l"(p));
    return a;
}

__device__ __forceinline__ float tf32_rnd(float x) {
    uint32_t u;
    asm("cvt.rna.tf32.f32 %0, %1;" : "=r"(u) : "f"(x));
    return __uint_as_float(u);
}

__device__ __forceinline__ void split4(float4 v, float4& h, float4& l) {
    h.x = tf32_rnd(v.x); l.x = tf32_rnd(v.x - h.x);
    h.y = tf32_rnd(v.y); l.y = tf32_rnd(v.y - h.y);
    h.z = tf32_rnd(v.z); l.z = tf32_rnd(v.z - h.z);
    h.w = tf32_rnd(v.w); l.w = tf32_rnd(v.w - h.w);
}

#define SWZ(o) ((o) ^ (((o) >> 3) & 0x70))

#ifdef TC_OK
__device__ __forceinline__ bool elect1() {
    uint32_t p;
    asm volatile("{\n\t.reg .pred p;\n\telect.sync _|p, 0xFFFFFFFF;\n\tselp.b32 %0,1,0,p;\n\t}" : "=r"(p));
    return p != 0;
}

#define TC_ALLOC(smaddr, n) \
    asm volatile("tcgen05.alloc.cta_group::1.sync.aligned.shared::cta.b32 [%0], %1;" :: "r"(smaddr), "r"(n) : "memory")
#define TC_RELINQ() \
    asm volatile("tcgen05.relinquish_alloc_permit.cta_group::1.sync.aligned;")
#define TC_DEALLOC(t, n) \
    asm volatile("tcgen05.dealloc.cta_group::1.sync.aligned.b32 %0, %1;" :: "r"(t), "r"(n))
#define TC_COMMIT(mbar) \
    asm volatile("tcgen05.commit.cta_group::1.mbarrier::arrive::one.shared::cluster.b64 [%0];" :: "r"(mbar) : "memory")
#define TC_FENCE_AFTER() \
    asm volatile("tcgen05.fence::after_thread_sync;" ::: "memory")
#define TC_WAIT_LD() \
    asm volatile("tcgen05.wait::ld.sync.aligned;" ::: "memory")
#define FENCE_ASYNC() \
    asm volatile("fence.proxy.async.shared::cta;" ::: "memory")
#define MBAR_INIT(a, c) \
    asm volatile("mbarrier.init.shared.b64 [%0], %1;" :: "r"(a), "r"(c) : "memory")
#define MBAR_INVAL(a) \
    asm volatile("mbarrier.inval.shared.b64 [%0];" :: "r"(a) : "memory")
#define MBWAIT(addr, ph) do { \
    asm volatile("{\n\t.reg .pred P1;\n\tWL%=:\n\t" \
        "mbarrier.try_wait.parity.acquire.cta.shared::cta.b64 P1, [%0], %1, 0x989680;\n\t" \
        "@P1 bra.uni WD%=;\n\tbra.uni WL%=;\n\tWD%=:\n\t}" \
        :: "r"(addr), "r"(ph) : "memory"); } while (0)

__device__ __forceinline__ void mma_tf32(uint32_t d, uint64_t ad, uint64_t bd, uint32_t idesc, uint32_t en) {
    uint32_t z = 0;
    asm volatile("{\n\t.reg .pred p;\n\tsetp.ne.u32 p, %5, 0;\n\t"
                 "tcgen05.mma.cta_group::1.kind::tf32 [%0], %1, %2, %3, {%4, %4, %4, %4}, p;\n\t}"
                 :: "r"(d), "l"(ad), "l"(bd), "r"(idesc), "r"(z), "r"(en) : "memory");
}

#define LDTM_X32(r, a) \
    asm volatile("tcgen05.ld.sync.aligned.32x32b.x32.b32 " \
        "{%0, %1, %2, %3, %4, %5, %6, %7, %8, %9, %10, %11, %12, %13, %14, %15, " \
        " %16, %17, %18, %19, %20, %21, %22, %23, %24, %25, %26, %27, %28, %29, %30, %31}, [%32];" \
        : "=r"((r)[0]),  "=r"((r)[1]),  "=r"((r)[2]),  "=r"((r)[3]), \
          "=r"((r)[4]),  "=r"((r)[5]),  "=r"((r)[6]),  "=r"((r)[7]), \
          "=r"((r)[8]),  "=r"((r)[9]),  "=r"((r)[10]), "=r"((r)[11]), \
          "=r"((r)[12]), "=r"((r)[13]), "=r"((r)[14]), "=r"((r)[15]), \
          "=r"((r)[16]), "=r"((r)[17]), "=r"((r)[18]), "=r"((r)[19]), \
          "=r"((r)[20]), "=r"((r)[21]), "=r"((r)[22]), "=r"((r)[23]), \
          "=r"((r)[24]), "=r"((r)[25]), "=r"((r)[26]), "=r"((r)[27]), \
          "=r"((r)[28]), "=r"((r)[29]), "=r"((r)[30]), "=r"((r)[31]) \
        : "r"(a))

// SW128 descriptor: layout=2, version=1, SBO=64, LBO=1 (K-major, 128B rows)
__device__ __forceinline__ uint64_t sdesc(uint32_t addr) {
    const uint64_t base = (uint64_t(2) << 61) | (uint64_t(1) << 46) |
                          (uint64_t(64) << 32) | (uint64_t(1) << 16);
    return base | ((uint64_t)(addr >> 4) & 0x3FFF);
}
#endif // TC_OK

// ================= tcgen05 tf32 (3x emulated fp32) GEMM =================
// C[M,Nn] = A[M,K] @ B[Nn,K]^T (both K-major). Active only in the 103a pass.
static const int SMEM_DYN = 2 * 4 * 16384 + 1024;

template<bool CSKIP, bool CKLIM, bool BIAS>
__global__ __launch_bounds__(128, 1)
void tgemm(const float* __restrict__ A, const float* __restrict__ B,
           float* __restrict__ C, const float* __restrict__ bias,
           int M, int Nn, int K, int lda, int ldb, int ldc,
           long long sA, long long sB, long long sC)
{
#ifdef TC_OK
    extern __shared__ char dsm[];
    __shared__ uint32_t s_tmem;
    __shared__ __align__(8) unsigned long long s_mbar[2];

    int m0 = blockIdx.y * 128, n0 = blockIdx.x * 128;
    if (CSKIP && n0 > m0 + 127) return;

    long long bz = blockIdx.z;
    A += bz * sA; B += bz * sB; C += bz * sC;

    uint32_t sb_raw = smem_u32(dsm);
    uint32_t sbase  = (sb_raw + 1023u) & ~1023u;
    char* baseg = dsm + (sbase - sb_raw);

    int tid = threadIdx.x;
    int wid = tid >> 5;
    int lid = tid & 31;

    uint32_t mb0 = smem_u32(&s_mbar[0]);
    uint32_t mb1 = smem_u32(&s_mbar[1]);

    if (wid == 0) {
        TC_ALLOC(smem_u32(&s_tmem), 128);
        TC_RELINQ();
    }
    if (tid == 0) { MBAR_INIT(mb0, 1); MBAR_INIT(mb1, 1); }
    __syncthreads();
    uint32_t tmem;
    asm("ld.shared.b32 %0, [%1];" : "=r"(tmem) : "r"(smem_u32(&s_tmem)));

    int kmax = K;
    if (CKLIM && m0 + 128 < kmax) kmax = m0 + 128;
    int nk = (kmax + 31) >> 5;

    const uint32_t IDESC = (1u << 4) | (2u << 7) | (2u << 10) | (16u << 17) | (8u << 24);

    int ph0 = 0, ph1 = 0;
    for (int kt = 0; kt < nk; kt++) {
        int b = kt & 1;
        uint32_t stoff = b ? 65536u : 0u;
        if (kt >= 2) {
            if (b == 0) { MBWAIT(mb0, ph0); ph0 ^= 1; }
            else        { MBWAIT(mb1, ph1); ph1 ^= 1; }
        }
        int k0 = kt << 5;
#pragma unroll
        for (int jj = 0; jj < 8; jj++) {
            int idx = tid + jj * 128;
            int r   = idx >> 3;
            int c4  = (idx & 7) << 2;
            int gk  = k0 + c4;
            uint32_t so = SWZ((uint32_t)(r * 128 + c4 * 4));

            float4 va = make_float4(0.f, 0.f, 0.f, 0.f);
            int gm = m0 + r;
            if (gm < M && gk + 4 <= K)
                va = *(const float4*)(A + (long long)gm * lda + gk);
            float4 h, l;
            split4(va, h, l);
            *(float4*)(baseg + stoff + so)          = h;
            *(float4*)(baseg + stoff + 16384u + so) = l;

            float4 vb = make_float4(0.f, 0.f, 0.f, 0.f);
            int gn = n0 + r;
            if (gn < Nn && gk + 4 <= K)
                vb = *(const float4*)(B + (long long)gn * ldb + gk);
            split4(vb, h, l);
            *(float4*)(baseg + stoff + 32768u + so) = h;
            *(float4*)(baseg + stoff + 49152u + so) = l;
        }
        FENCE_ASYNC();
        __syncthreads();

        if (wid == 0 && elect1()) {
            uint64_t da_hi = sdesc(sbase + stoff);
            uint64_t da_lo = sdesc(sbase + stoff + 16384u);
            uint64_t db_hi = sdesc(sbase + stoff + 32768u);
            uint64_t db_lo = sdesc(sbase + stoff + 49152u);
#pragma unroll
            for (int ks = 0; ks < 4; ks++) {
                uint32_t en = (kt > 0 || ks > 0) ? 1u : 0u;
                mma_tf32(tmem, da_hi + ks * 2, db_hi + ks * 2, IDESC, en);
                mma_tf32(tmem, da_hi + ks * 2, db_lo + ks * 2, IDESC, 1u);
                mma_tf32(tmem, da_lo + ks * 2, db_hi + ks * 2, IDESC, 1u);
            }
            TC_COMMIT(b ? mb1 : mb0);
        }
    }

    if (nk >= 2) {
        int b = (nk - 2) & 1;
        if (b == 0) { MBWAIT(mb0, ph0); ph0 ^= 1; }
        else        { MBWAIT(mb1, ph1); ph1 ^= 1; }
    }
    {
        int b = (nk - 1) & 1;
        if (b == 0) { MBWAIT(mb0, ph0); ph0 ^= 1; }
        else        { MBWAIT(mb1, ph1); ph1 ^= 1; }
    }
    TC_FENCE_AFTER();

    int gm = m0 + wid * 32 + lid;
#pragma unroll
    for (int base = 0; base < 128; base += 32) {
        uint32_t r[32];
        LDTM_X32(r, tmem + base);
        TC_WAIT_LD();
        if (gm < M) {
#pragma unroll
            for (int c = 0; c < 32; c += 4) {
                int gn = n0 + base + c;
                if (gn + 4 <= Nn) {
                    float4 v;
                    v.x = __uint_as_float(r[c + 0]);
                    v.y = __uint_as_float(r[c + 1]);
                    v.z = __uint_as_float(r[c + 2]);
                    v.w = __uint_as_float(r[c + 3]);
                    if (BIAS) {
                        v.x += bias[gn + 0]; v.y += bias[gn + 1];
                        v.z += bias[gn + 2]; v.w += bias[gn + 3];
                    }
                    *(float4*)(C + (long long)gm * ldc + gn) = v;
                }
            }
        }
    }

    __syncthreads();
    if (tid == 0) { MBAR_INVAL(mb0); MBAR_INVAL(mb1); }
    if (wid == 0) { TC_DEALLOC(tmem, 128); }
#endif // TC_OK
}

// ================= FFMA fallback GEMM (plain sm_103 pass only) =================
template<bool CSKIP, bool CKLIM, bool BIAS>
__global__ __launch_bounds__(256, 2)
void ffgemm(const float* __restrict__ A, const float* __restrict__ B,
            float* __restrict__ C, const float* __restrict__ bias,
            int M, int Nn, int K, int lda, int ldb, int ldc,
            long long sA, long long sB, long long sC)
{
#ifndef TC_OK
    const int BM = 128, BN = 128, BK = 16;
    __shared__ float As[BK][BM];
    __shared__ float Bs[BK][BN];

    int bz = blockIdx.z;
    A += (long long)bz * sA;
    B += (long long)bz * sB;
    C += (long long)bz * sC;

    int m0 = blockIdx.y * BM;
    int n0 = blockIdx.x * BN;
    if (CSKIP && n0 > m0 + BM - 1) return;

    int tid  = threadIdx.x;
    int trow = tid >> 4;
    int tcol = tid & 15;

    float acc[8][8];
#pragma unroll
    for (int i = 0; i < 8; i++)
#pragma unroll
        for (int j = 0; j < 8; j++) acc[i][j] = 0.f;

    int ktiles = (K + BK - 1) / BK;
    if (CKLIM) {
        int kl = (m0 + BM + BK - 1) / BK;
        if (kl < ktiles) ktiles = kl;
    }

    for (int kt = 0; kt < ktiles; kt++) {
        int k0 = kt * BK;
#pragma unroll
        for (int jj = 0; jj < 2; jj++) {
            int i  = tid + jj * 256;
            int r  = i >> 2;
            int c4 = (i & 3) * 4;
            float4 v = make_float4(0.f, 0.f, 0.f, 0.f);
            int gr = m0 + r;
            if (gr < M && (k0 + c4 + 4) <= K)
                v = *(const float4*)(A + (long long)gr * lda + k0 + c4);
            As[c4 + 0][r] = v.x;
            As[c4 + 1][r] = v.y;
            As[c4 + 2][r] = v.z;
            As[c4 + 3][r] = v.w;
        }
#pragma unroll
        for (int jj = 0; jj < 2; jj++) {
            int i  = tid + jj * 256;
            int r  = i >> 2;
            int c4 = (i & 3) * 4;
            float4 v = make_float4(0.f, 0.f, 0.f, 0.f);
            int gr = n0 + r;
            if (gr < Nn && (k0 + c4 + 4) <= K)
                v = *(const float4*)(B + (long long)gr * ldb + k0 + c4);
            Bs[c4 + 0][r] = v.x;
            Bs[c4 + 1][r] = v.y;
            Bs[c4 + 2][r] = v.z;
            Bs[c4 + 3][r] = v.w;
        }
        __syncthreads();

#pragma unroll
        for (int kk = 0; kk < BK; kk++) {
            float a[8], b[8];
            *(float4*)&a[0] = *(const float4*)&As[kk][trow * 8];
            *(float4*)&a[4] = *(const float4*)&As[kk][trow * 8 + 4];
            *(float4*)&b[0] = *(const float4*)&Bs[kk][tcol * 8];
            *(float4*)&b[4] = *(const float4*)&Bs[kk][tcol * 8 + 4];
#pragma unroll
            for (int i = 0; i < 8; i++)
#pragma unroll
                for (int j = 0; j < 8; j++)
                    acc[i][j] += a[i] * b[j];
        }
        __syncthreads();
    }

#pragma unroll
    for (int i = 0; i < 8; i++) {
        int gm = m0 + trow * 8 + i;
        if (gm >= M) continue;
#pragma unroll
        for (int j = 0; j < 8; j++) {
            int gn = n0 + tcol * 8 + j;
            if (gn >= Nn) continue;
            float v = acc[i][j];
            if (BIAS) v += bias[gn];
            C[(long long)gm * ldc + gn] = v;
        }
    }
#endif // !TC_OK
}

// ---------------- positional encoding + input add ----------------
__global__ void build_x_kernel(const float* __restrict__ inp,
                               const float* __restrict__ inp2)
{
    int idx = blockIdx.x * blockDim.x + threadIdx.x;
    if (idx >= LL * DD) return;
    int l = idx / DD;
    int j = idx % DD;
    float rate = expf(-(float)j * 8.99447363e-3f);
    float ang  = (float)l * rate;
    float pe   = (j & 1) ? cosf(ang) : sinf(ang);
#pragma unroll
    for (int n = 0; n < NB; n++) {
        long long o = (long long)n * LL * DD + idx;
        g_x [o] = inp [o] + pe;
        g_xu[o] = inp2[o] + pe;
    }
}

// ---------------- causal softmax (in-place on S -> P) ----------------
__global__ void softmax_causal_kernel(float* __restrict__ S)
{
    int q = blockIdx.x;
    int n = blockIdx.y;
    float* row = S + ((long long)n * LL + q) * (long long)LL;
    int len = q + 1;
    int tid = threadIdx.x;
    __shared__ float red[256];

    float mx = -3.4e38f;
    for (int k = tid; k < len; k += 256) mx = fmaxf(mx, row[k]);
    red[tid] = mx;
    __syncthreads();
    for (int s = 128; s > 0; s >>= 1) {
        if (tid < s) red[tid] = fmaxf(red[tid], red[tid + s]);
        __syncthreads();
    }
    mx = red[0];
    __syncthreads();

    float sum = 0.f;
    for (int k = tid; k < len; k += 256) {
        float e = expf(row[k] - mx);
        row[k] = e;
        sum += e;
    }
    red[tid] = sum;
    __syncthreads();
    for (int s = 128; s > 0; s >>= 1) {
        if (tid < s) red[tid] += red[tid + s];
        __syncthreads();
    }
    float inv = 1.f / red[0];

    for (int k = tid; k < len; k += 256) row[k] *= inv;
    for (int k = len + tid; k < LL; k += 256) row[k] = 0.f;
}

// ---------------- combine + residual + layernorm ----------------
__global__ void fuse_ln_kernel(const float* __restrict__ inp,
                               const float* __restrict__ ln_g,
                               const float* __restrict__ ln_b)
{
    int r = blockIdx.x;
    long long base = (long long)r * DD;
    const float* o1 = g_o1 + base;
    const float* o2 = g_o2 + base;
    const float* xr = inp  + base;
    float*       yn = g_yn + base;
    int tid = threadIdx.x;

    __shared__ float ssum[256];
    __shared__ float ssq [256];

    float v[4];
    float s = 0.f, s2 = 0.f;
#pragma unroll
    for (int i = 0; i < 4; i++) {
        int d = tid + i * 256;
        float y = 0.5f * (o1[d] + o2[d]) + xr[d];
        v[i] = y;
        s  += y;
        s2 += y * y;
    }
    ssum[tid] = s;
    ssq [tid] = s2;
    __syncthreads();
    for (int st = 128; st > 0; st >>= 1) {
        if (tid < st) { ssum[tid] += ssum[tid + st]; ssq[tid] += ssq[tid + st]; }
        __syncthreads();
    }
    float mu  = ssum[0] * (1.f / DD);
    float var = ssq[0]  * (1.f / DD) - mu * mu;
    float inv = rsqrtf(var + 1e-5f);
#pragma unroll
    for (int i = 0; i < 4; i++) {
        int d = tid + i * 256;
        yn[d] = (v[i] - mu) * inv * ln_g[d] + ln_b[d];
    }
}

// ---------------- host launch ----------------
#define GB(T1, T2, T3, grid, A_, B_, C_, bias_, M_, N_, K_, lda_, ldb_, ldc_, sA_, sB_, sC_) \
    do { \
        tgemm<T1, T2, T3><<<grid, 128, SMEM_DYN>>>(A_, B_, C_, bias_, M_, N_, K_, lda_, ldb_, ldc_, sA_, sB_, sC_); \
        ffgemm<T1, T2, T3><<<grid, 256>>>(A_, B_, C_, bias_, M_, N_, K_, lda_, ldb_, ldc_, sA_, sB_, sC_); \
    } while (0)

extern "C" void kernel_launch(void* const* d_in, const int* in_sizes, int n_in,
                              void* d_out, int out_size)
{
    const float* inputs  = (const float*)d_in[0];
    const float* inputs2 = (const float*)d_in[1];
    const float* Wq      = (const float*)d_in[2];
    const float* Wqu     = (const float*)d_in[3];
    const float* Wk      = (const float*)d_in[4];
    const float* Wv      = (const float*)d_in[5];
    // d_in[6] W_d, d_in[7] h_vec: dead code (A == 0.5 exactly in the reference)
    const float* fc_w    = (const float*)d_in[8];
    const float* fc_b    = (const float*)d_in[9];
    const float* ln_g    = (const float*)d_in[10];
    const float* ln_b    = (const float*)d_in[11];
    float* out = (float*)d_out;

    float *x, *xu, *qh, *kh, *vt, *quh, *s1, *s2, *o1, *o2, *yn;
    cudaGetSymbolAddress((void**)&x,   g_x);
    cudaGetSymbolAddress((void**)&xu,  g_xu);
    cudaGetSymbolAddress((void**)&qh,  g_qh);
    cudaGetSymbolAddress((void**)&kh,  g_kh);
    cudaGetSymbolAddress((void**)&vt,  g_vt);
    cudaGetSymbolAddress((void**)&quh, g_quh);
    cudaGetSymbolAddress((void**)&s1,  g_s1);
    cudaGetSymbolAddress((void**)&s2,  g_s2);
    cudaGetSymbolAddress((void**)&o1,  g_o1);
    cudaGetSymbolAddress((void**)&o2,  g_o2);
    cudaGetSymbolAddress((void**)&yn,  g_yn);

    cudaFuncSetAttribute(tgemm<false, false, false>, cudaFuncAttributeMaxDynamicSharedMemorySize, SMEM_DYN);
    cudaFuncSetAttribute(tgemm<true,  false, false>, cudaFuncAttributeMaxDynamicSharedMemorySize, SMEM_DYN);
    cudaFuncSetAttribute(tgemm<false, true,  false>, cudaFuncAttributeMaxDynamicSharedMemorySize, SMEM_DYN);
    cudaFuncSetAttribute(tgemm<false, false, true >, cudaFuncAttributeMaxDynamicSharedMemorySize, SMEM_DYN);

    const long long sQK = (long long)LL * DD;
    const long long sS  = (long long)LL * LL;

    // 1. x = inputs + pe, xu = inputs2 + pe
    build_x_kernel<<<(LL * DD + 255) / 256, 256>>>(inputs, inputs2);

    // 2. projections: Q/K/QU = [16000,1024] @ W^T
    dim3 gp(8, 125, 1);
    GB(false, false, false, gp, x,  Wq,  qh,  (const float*)nullptr, MM, DD, DD, DD, DD, DD, 0LL, 0LL, 0LL);
    GB(false, false, false, gp, x,  Wk,  kh,  (const float*)nullptr, MM, DD, DD, DD, DD, DD, 0LL, 0LL, 0LL);
    GB(false, false, false, gp, xu, Wqu, quh, (const float*)nullptr, MM, DD, DD, DD, DD, DD, 0LL, 0LL, 0LL);

    //    Vt = Wv @ x^T per batch : [1024, 1000]
    dim3 gv(8, 8, NB);
    GB(false, false, false, gv, Wv, x, vt, (const float*)nullptr, DD, LL, DD, DD, DD, LL, 0LL, sQK, sQK);

    // 3. scores (causal tile skip): S = Q @ K^T per batch
    dim3 gs(8, 8, NB);
    GB(true, false, false, gs, qh,  kh, s1, (const float*)nullptr, LL, LL, DD, DD, DD, LL, sQK, sQK, sS);
    GB(true, false, false, gs, quh, kh, s2, (const float*)nullptr, LL, LL, DD, DD, DD, LL, sQK, sQK, sS);

    // 4. causal softmax in place
    dim3 gsm(LL, NB);
    softmax_causal_kernel<<<gsm, 256>>>(s1);
    softmax_causal_kernel<<<gsm, 256>>>(s2);

    // 5. O = P @ Vt^T per batch (K capped at m0+128 via CKLIM)
    dim3 gpv(8, 8, NB);
    GB(false, true, false, gpv, s1, vt, o1, (const float*)nullptr, LL, DD, LL, LL, LL, DD, sS, sQK, sQK);
    GB(false, true, false, gpv, s2, vt, o2, (const float*)nullptr, LL, DD, LL, LL, LL, DD, sS, sQK, sQK);

    // 6. y = 0.5*(o1+o2) + inputs; layernorm -> yn
    fuse_ln_kernel<<<MM, 256>>>(inputs, ln_g, ln_b);

    // 7. out = yn @ fc_w^T + fc_b
    GB(false, false, true, gp, yn, fc_w, out, fc_b, MM, DD, DD, DD, DD, DD, 0LL, 0LL, 0LL);
}

// round 4
// speedup vs baseline: 3.7776x; 2.1598x over previous
#include <cuda_runtime.h>
#include <cstdint>
#include <math.h>

#define NB 16
#define LL 1000
#define DD 1024
#define MM (NB*LL)   // 16000

// Arch-feature gate: tcgen05 path only in the compute_103a pass; the plain
// compute_103 pass compiles the FFMA fallback. Host launches both (one is a no-op).
#if defined(__CUDA_ARCH__) && (defined(__CUDA_ARCH_FEAT_SM103_ALL) || defined(__CUDA_ARCH_FEAT_SM100_ALL))
#define TC_OK 1
#endif

// ---------------- scratch (static device globals; no allocation) ----------------
// All GEMM operands stored PRE-SPLIT as (hi, lo) tf32 pairs: hi = tf32(v), lo = tf32(v-hi)... lo stored fp32.
__device__ float g_xh  [NB*LL*DD];
__device__ float g_xl  [NB*LL*DD];
__device__ float g_xuh [NB*LL*DD];
__device__ float g_xul [NB*LL*DD];
__device__ float g_qhh [NB*LL*DD];
__device__ float g_qhl [NB*LL*DD];
__device__ float g_khh [NB*LL*DD];
__device__ float g_khl [NB*LL*DD];
__device__ float g_quhh[NB*LL*DD];
__device__ float g_quhl[NB*LL*DD];
__device__ float g_vth [NB*DD*LL];   // V transposed: [batch][1024][1000]
__device__ float g_vtl [NB*DD*LL];
__device__ float g_s1  [NB*LL*LL];   // scores -> p_hi (in place)
__device__ float g_s1l [NB*LL*LL];   // p_lo
__device__ float g_s2  [NB*LL*LL];
__device__ float g_s2l [NB*LL*LL];
__device__ float g_o1  [NB*LL*DD];
__device__ float g_o2  [NB*LL*DD];
__device__ float g_ynh [NB*LL*DD];
__device__ float g_ynl [NB*LL*DD];
__device__ float g_wh  [5*DD*DD];    // Wq, Wk, Wqu, Wv, fc_w hi
__device__ float g_wl  [5*DD*DD];    // lo

// ================= helpers =================
__device__ __forceinline__ uint32_t smem_u32(const void* p) {
    uint32_t a;
    asm("{ .reg .u64 t; cvta.to.shared.u64 t, %1; cvt.u32.u64 %0, t; }" : "=r"(a) : "l"(p));
    return a;
}

__device__ __forceinline__ float tf32_rnd(float x) {
    uint32_t u;
    asm("cvt.rna.tf32.f32 %0, %1;" : "=r"(u) : "f"(x));
    return __uint_as_float(u);
}

__device__ __forceinline__ void split4(float4 v, float4& h, float4& l) {
    h.x = tf32_rnd(v.x); l.x = v.x - h.x;
    h.y = tf32_rnd(v.y); l.y = v.y - h.y;
    h.z = tf32_rnd(v.z); l.z = v.z - h.z;
    h.w = tf32_rnd(v.w); l.w = v.w - h.w;
}

#define SWZ(o) ((o) ^ (((o) >> 3) & 0x70))

#ifdef TC_OK
__device__ __forceinline__ bool elect1() {
    uint32_t p;
    asm volatile("{\n\t.reg .pred p;\n\telect.sync _|p, 0xFFFFFFFF;\n\tselp.b32 %0,1,0,p;\n\t}" : "=r"(p));
    return p != 0;
}

#define TC_ALLOC(smaddr, n) \
    asm volatile("tcgen05.alloc.cta_group::1.sync.aligned.shared::cta.b32 [%0], %1;" :: "r"(smaddr), "r"(n) : "memory")
#define TC_RELINQ() \
    asm volatile("tcgen05.relinquish_alloc_permit.cta_group::1.sync.aligned;")
#define TC_DEALLOC(t, n) \
    asm volatile("tcgen05.dealloc.cta_group::1.sync.aligned.b32 %0, %1;" :: "r"(t), "r"(n))
#define TC_COMMIT(mbar) \
    asm volatile("tcgen05.commit.cta_group::1.mbarrier::arrive::one.shared::cluster.b64 [%0];" :: "r"(mbar) : "memory")
#define TC_FENCE_AFTER() \
    asm volatile("tcgen05.fence::after_thread_sync;" ::: "memory")
#define TC_WAIT_LD() \
    asm volatile("tcgen05.wait::ld.sync.aligned;" ::: "memory")
#define FENCE_ASYNC() \
    asm volatile("fence.proxy.async.shared::cta;" ::: "memory")
#define MBAR_INIT(a, c) \
    asm volatile("mbarrier.init.shared.b64 [%0], %1;" :: "r"(a), "r"(c) : "memory")
#define MBAR_INVAL(a) \
    asm volatile("mbarrier.inval.shared.b64 [%0];" :: "r"(a) : "memory")
#define MBWAIT(addr, ph) do { \
    asm volatile("{\n\t.reg .pred P1;\n\tWL%=:\n\t" \
        "mbarrier.try_wait.parity.acquire.cta.shared::cta.b64 P1, [%0], %1, 0x989680;\n\t" \
        "@P1 bra.uni WD%=;\n\tbra.uni WL%=;\n\tWD%=:\n\t}" \
        :: "r"(addr), "r"(ph) : "memory"); } while (0)

#define CP_ASYNC(dst, src, sz) \
    asm volatile("cp.async.cg.shared.global [%0], [%1], 16, %2;" \
        :: "r"(dst), "l"(src), "r"(sz) : "memory")
#define CP_COMMIT() asm volatile("cp.async.commit_group;" ::: "memory")
#define CP_WAIT(n)  asm volatile("cp.async.wait_group %0;" :: "n"(n) : "memory")

__device__ __forceinline__ void mma_tf32(uint32_t d, uint64_t ad, uint64_t bd, uint32_t idesc, uint32_t en) {
    uint32_t z = 0;
    asm volatile("{\n\t.reg .pred p;\n\tsetp.ne.u32 p, %5, 0;\n\t"
                 "tcgen05.mma.cta_group::1.kind::tf32 [%0], %1, %2, %3, {%4, %4, %4, %4}, p;\n\t}"
                 :: "r"(d), "l"(ad), "l"(bd), "r"(idesc), "r"(z), "r"(en) : "memory");
}

#define LDTM_X32(r, a) \
    asm volatile("tcgen05.ld.sync.aligned.32x32b.x32.b32 " \
        "{%0, %1, %2, %3, %4, %5, %6, %7, %8, %9, %10, %11, %12, %13, %14, %15, " \
        " %16, %17, %18, %19, %20, %21, %22, %23, %24, %25, %26, %27, %28, %29, %30, %31}, [%32];" \
        : "=r"((r)[0]),  "=r"((r)[1]),  "=r"((r)[2]),  "=r"((r)[3]), \
          "=r"((r)[4]),  "=r"((r)[5]),  "=r"((r)[6]),  "=r"((r)[7]), \
          "=r"((r)[8]),  "=r"((r)[9]),  "=r"((r)[10]), "=r"((r)[11]), \
          "=r"((r)[12]), "=r"((r)[13]), "=r"((r)[14]), "=r"((r)[15]), \
          "=r"((r)[16]), "=r"((r)[17]), "=r"((r)[18]), "=r"((r)[19]), \
          "=r"((r)[20]), "=r"((r)[21]), "=r"((r)[22]), "=r"((r)[23]), \
          "=r"((r)[24]), "=r"((r)[25]), "=r"((r)[26]), "=r"((r)[27]), \
          "=r"((r)[28]), "=r"((r)[29]), "=r"((r)[30]), "=r"((r)[31]) \
        : "r"(a))

// SW128 descriptor: layout=2, version=1, SBO=64, LBO=1 (K-major, 128B rows)
__device__ __forceinline__ uint64_t sdesc(uint32_t addr) {
    const uint64_t base = (uint64_t(2) << 61) | (uint64_t(1) << 46) |
                          (uint64_t(64) << 32) | (uint64_t(1) << 16);
    return base | ((uint64_t)(addr >> 4) & 0x3FFF);
}
#endif // TC_OK

// ================= tcgen05 tf32x3 GEMM, cp.async 3-stage pipeline =================
// C[M,Nn] = A[M,K] @ B[Nn,K]^T, operands pre-split (Ah,Al,Bh,Bl), K-major.
#define ST 3
#define STAGE_BYTES 65536
static const int SMEM_DYN = ST * STAGE_BYTES + 1024;

template<bool CSKIP, bool CKLIM, bool BIAS, bool SPLITOUT>
__global__ __launch_bounds__(256, 1)
void tgemm(const float* __restrict__ Ah, const float* __restrict__ Al,
           const float* __restrict__ Bh, const float* __restrict__ Bl,
           float* __restrict__ C, float* __restrict__ Cl, const float* __restrict__ bias,
           int M, int Nn, int K, int lda, int ldb, int ldc,
           long long sA, long long sB, long long sC)
{
#ifdef TC_OK
    extern __shared__ char dsm[];
    __shared__ uint32_t s_tmem;
    __shared__ __align__(8) unsigned long long s_mbar[ST];

    int m0 = blockIdx.y * 128, n0 = blockIdx.x * 128;
    if (CSKIP && n0 > m0 + 127) return;

    long long bz = blockIdx.z;
    Ah += bz * sA; Al += bz * sA; Bh += bz * sB; Bl += bz * sB;
    C += bz * sC; Cl += bz * sC;

    uint32_t sb_raw = smem_u32(dsm);
    uint32_t sbase  = (sb_raw + 1023u) & ~1023u;

    int tid = threadIdx.x;
    int wid = tid >> 5;
    int lid = tid & 31;

    if (wid == 0) { TC_ALLOC(smem_u32(&s_tmem), 128); TC_RELINQ(); }
    if (tid < ST) MBAR_INIT(smem_u32(&s_mbar[tid]), 1);
    __syncthreads();
    uint32_t tmem;
    asm("ld.shared.b32 %0, [%1];" : "=r"(tmem) : "r"(smem_u32(&s_tmem)));

    int kmax = K;
    if (CKLIM && m0 + 128 < kmax) kmax = m0 + 128;
    int nk = (kmax + 31) >> 5;

    const uint32_t IDESC = (1u << 4) | (2u << 7) | (2u << 10) | (16u << 17) | (8u << 24);

    // issue all cp.asyncs for one K-chunk into its stage; zero-fill OOB
    auto load_chunk = [&](int c) {
        uint32_t stg = sbase + (uint32_t)(c % ST) * STAGE_BYTES;
        int k0 = c << 5;
#pragma unroll
        for (int i = 0; i < 4; i++) {
            int idx = tid + i * 256;
            int r   = idx >> 3;
            int c4  = (idx & 7) << 2;
            uint32_t so = SWZ((uint32_t)(r * 128 + c4 * 4));
            int gk = k0 + c4;
            {
                int gm = m0 + r;
                int sz = (gm < M && gk < K) ? 16 : 0;
                const float* sh = Ah + (long long)gm * lda + gk;
                const float* sl = Al + (long long)gm * lda + gk;
                CP_ASYNC(stg + so,           sh, sz);
                CP_ASYNC(stg + 16384u + so,  sl, sz);
            }
            {
                int gn = n0 + r;
                int sz = (gn < Nn && gk < K) ? 16 : 0;
                const float* sh = Bh + (long long)gn * ldb + gk;
                const float* sl = Bl + (long long)gn * ldb + gk;
                CP_ASYNC(stg + 32768u + so,  sh, sz);
                CP_ASYNC(stg + 49152u + so,  sl, sz);
            }
        }
        CP_COMMIT();
    };

    bool mma_thread;
    if (wid == 0) mma_thread = elect1(); else mma_thread = false;

    // prologue: stages 0..ST-2
    for (int s = 0; s < ST - 1 && s < nk; s++) load_chunk(s);

    for (int kt = 0; kt < nk; kt++) {
        // ensure chunk kt's cp.async group is done (groups commit in chunk order)
        int pend = nk - 1 - kt; if (pend > ST - 2) pend = ST - 2;
        if (pend >= 1) { CP_WAIT(1); } else { CP_WAIT(0); }
        FENCE_ASYNC();
        __syncthreads();

        // issue MMAs for chunk kt FIRST (keeps tensor queue fed), then prefetch
        if (mma_thread) {
            uint32_t stg = sbase + (uint32_t)(kt % ST) * STAGE_BYTES;
            uint64_t dah = sdesc(stg);
            uint64_t dal = sdesc(stg + 16384u);
            uint64_t dbh = sdesc(stg + 32768u);
            uint64_t dbl = sdesc(stg + 49152u);
#pragma unroll
            for (int ks = 0; ks < 4; ks++) {
                uint32_t en = (kt > 0 || ks > 0) ? 1u : 0u;
                mma_tf32(tmem, dah + ks * 2, dbh + ks * 2, IDESC, en);
                mma_tf32(tmem, dah + ks * 2, dbl + ks * 2, IDESC, 1u);
                mma_tf32(tmem, dal + ks * 2, dbh + ks * 2, IDESC, 1u);
            }
            TC_COMMIT(smem_u32(&s_mbar[kt % ST]));
        }

        // prefetch chunk kt+ST-1 into its stage (wait MMA of chunk kt-1 to free it)
        int c = kt + ST - 1;
        if (c < nk) {
            if (c >= ST) {
                int m = c / ST;
                MBWAIT(smem_u32(&s_mbar[c % ST]), (m - 1) & 1);
            }
            load_chunk(c);
        }
    }

    // drain: wait final chunk's MMA commit
    if (tid == 0) {
        int m = (nk - 1) / ST;
        MBWAIT(smem_u32(&s_mbar[(nk - 1) % ST]), m & 1);
    }
    __syncthreads();
    TC_FENCE_AFTER();

    // epilogue: 8 warps; warp w -> rows (w%4)*32, cols (w/4)*64
    int gm = m0 + (wid & 3) * 32 + lid;
    int cb = (wid >> 2) * 64;
#pragma unroll
    for (int half = 0; half < 2; half++) {
        uint32_t r[32];
        int cc = cb + half * 32;
        LDTM_X32(r, tmem + cc);
        TC_WAIT_LD();
        if (gm < M) {
#pragma unroll
            for (int c = 0; c < 32; c += 4) {
                int gn = n0 + cc + c;
                if (gn + 4 <= Nn) {
                    float4 v;
                    v.x = __uint_as_float(r[c + 0]);
                    v.y = __uint_as_float(r[c + 1]);
                    v.z = __uint_as_float(r[c + 2]);
                    v.w = __uint_as_float(r[c + 3]);
                    if (BIAS) {
                        v.x += bias[gn + 0]; v.y += bias[gn + 1];
                        v.z += bias[gn + 2]; v.w += bias[gn + 3];
                    }
                    if (SPLITOUT) {
                        float4 h, l;
                        split4(v, h, l);
                        *(float4*)(C  + (long long)gm * ldc + gn) = h;
                        *(float4*)(Cl + (long long)gm * ldc + gn) = l;
                    } else {
                        *(float4*)(C + (long long)gm * ldc + gn) = v;
                    }
                }
            }
        }
    }

    __syncthreads();
    if (tid < ST) MBAR_INVAL(smem_u32(&s_mbar[tid]));
    if (wid == 0) TC_DEALLOC(tmem, 128);
#endif // TC_OK
}

// ================= FFMA fallback GEMM (plain sm_103 pass only) =================
template<bool CSKIP, bool CKLIM, bool BIAS, bool SPLITOUT>
__global__ __launch_bounds__(256, 2)
void ffgemm(const float* __restrict__ Ah, const float* __restrict__ Al,
            const float* __restrict__ Bh, const float* __restrict__ Bl,
            float* __restrict__ C, float* __restrict__ Cl, const float* __restrict__ bias,
            int M, int Nn, int K, int lda, int ldb, int ldc,
            long long sA, long long sB, long long sC)
{
#ifndef TC_OK
    const int BM = 128, BN = 128, BK = 16;
    __shared__ float As[BK][BM];
    __shared__ float Bs[BK][BN];

    int bz = blockIdx.z;
    Ah += (long long)bz * sA; Al += (long long)bz * sA;
    Bh += (long long)bz * sB; Bl += (long long)bz * sB;
    C += (long long)bz * sC;  Cl += (long long)bz * sC;

    int m0 = blockIdx.y * BM;
    int n0 = blockIdx.x * BN;
    if (CSKIP && n0 > m0 + BM - 1) return;

    int tid  = threadIdx.x;
    int trow = tid >> 4;
    int tcol = tid & 15;

    float acc[8][8];
#pragma unroll
    for (int i = 0; i < 8; i++)
#pragma unroll
        for (int j = 0; j < 8; j++) acc[i][j] = 0.f;

    int ktiles = (K + BK - 1) / BK;
    if (CKLIM) {
        int kl = (m0 + BM + BK - 1) / BK;
        if (kl < ktiles) ktiles = kl;
    }

    for (int kt = 0; kt < ktiles; kt++) {
        int k0 = kt * BK;
#pragma unroll
        for (int jj = 0; jj < 2; jj++) {
            int i  = tid + jj * 256;
            int r  = i >> 2;
            int c4 = (i & 3) * 4;
            float4 v = make_float4(0.f, 0.f, 0.f, 0.f);
            int gr = m0 + r;
            if (gr < M && (k0 + c4 + 4) <= K) {
                float4 h = *(const float4*)(Ah + (long long)gr * lda + k0 + c4);
                float4 l = *(const float4*)(Al + (long long)gr * lda + k0 + c4);
                v = make_float4(h.x + l.x, h.y + l.y, h.z + l.z, h.w + l.w);
            }
            As[c4 + 0][r] = v.x; As[c4 + 1][r] = v.y;
            As[c4 + 2][r] = v.z; As[c4 + 3][r] = v.w;
        }
#pragma unroll
        for (int jj = 0; jj < 2; jj++) {
            int i  = tid + jj * 256;
            int r  = i >> 2;
            int c4 = (i & 3) * 4;
            float4 v = make_float4(0.f, 0.f, 0.f, 0.f);
            int gr = n0 + r;
            if (gr < Nn && (k0 + c4 + 4) <= K) {
                float4 h = *(const float4*)(Bh + (long long)gr * ldb + k0 + c4);
                float4 l = *(const float4*)(Bl + (long long)gr * ldb + k0 + c4);
                v = make_float4(h.x + l.x, h.y + l.y, h.z + l.z, h.w + l.w);
            }
            Bs[c4 + 0][r] = v.x; Bs[c4 + 1][r] = v.y;
            Bs[c4 + 2][r] = v.z; Bs[c4 + 3][r] = v.w;
        }
        __syncthreads();

#pragma unroll
        for (int kk = 0; kk < BK; kk++) {
            float a[8], b[8];
            *(float4*)&a[0] = *(const float4*)&As[kk][trow * 8];
            *(float4*)&a[4] = *(const float4*)&As[kk][trow * 8 + 4];
            *(float4*)&b[0] = *(const float4*)&Bs[kk][tcol * 8];
            *(float4*)&b[4] = *(const float4*)&Bs[kk][tcol * 8 + 4];
#pragma unroll
            for (int i = 0; i < 8; i++)
#pragma unroll
                for (int j = 0; j < 8; j++)
                    acc[i][j] += a[i] * b[j];
        }
        __syncthreads();
    }

#pragma unroll
    for (int i = 0; i < 8; i++) {
        int gm = m0 + trow * 8 + i;
        if (gm >= M) continue;
#pragma unroll
        for (int j = 0; j < 8; j++) {
            int gn = n0 + tcol * 8 + j;
            if (gn >= Nn) continue;
            float v = acc[i][j];
            if (BIAS) v += bias[gn];
            if (SPLITOUT) {
                float h = tf32_rnd(v);
                C [(long long)gm * ldc + gn] = h;
                Cl[(long long)gm * ldc + gn] = v - h;
            } else {
                C[(long long)gm * ldc + gn] = v;
            }
        }
    }
#endif // !TC_OK
}

// ---------------- positional encoding + input add (split output) ----------------
__global__ void build_x_kernel(const float* __restrict__ inp,
                               const float* __restrict__ inp2)
{
    int idx = blockIdx.x * blockDim.x + threadIdx.x;
    if (idx >= LL * DD) return;
    int l = idx / DD;
    int j = idx % DD;
    float rate = expf(-(float)j * 8.99447363e-3f);
    float ang  = (float)l * rate;
    float pe   = (j & 1) ? cosf(ang) : sinf(ang);
#pragma unroll
    for (int n = 0; n < NB; n++) {
        long long o = (long long)n * LL * DD + idx;
        float v = inp[o] + pe;
        float h = tf32_rnd(v);
        g_xh[o] = h; g_xl[o] = v - h;
        v = inp2[o] + pe;
        h = tf32_rnd(v);
        g_xuh[o] = h; g_xul[o] = v - h;
    }
}

// ---------------- weight split ----------------
__global__ void wsplit_kernel(const float* __restrict__ src, float* __restrict__ hi,
                              float* __restrict__ lo, int n)
{
    int i = blockIdx.x * blockDim.x + threadIdx.x;
    if (i >= n) return;
    float v = src[i];
    float h = tf32_rnd(v);
    hi[i] = h; lo[i] = v - h;
}

// ---------------- causal softmax (in-place on S -> P hi, plus lo) ----------------
__global__ void softmax_causal_kernel(float* __restrict__ S, float* __restrict__ Slo)
{
    int q = blockIdx.x;
    int n = blockIdx.y;
    long long roff = ((long long)n * LL + q) * (long long)LL;
    float* row = S + roff;
    float* rlo = Slo + roff;
    int len = q + 1;
    int tid = threadIdx.x;
    __shared__ float red[256];

    float mx = -3.4e38f;
    for (int k = tid; k < len; k += 256) mx = fmaxf(mx, row[k]);
    red[tid] = mx;
    __syncthreads();
    for (int s = 128; s > 0; s >>= 1) {
        if (tid < s) red[tid] = fmaxf(red[tid], red[tid + s]);
        __syncthreads();
    }
    mx = red[0];
    __syncthreads();

    float sum = 0.f;
    for (int k = tid; k < len; k += 256) {
        float e = expf(row[k] - mx);
        row[k] = e;
        sum += e;
    }
    red[tid] = sum;
    __syncthreads();
    for (int s = 128; s > 0; s >>= 1) {
        if (tid < s) red[tid] += red[tid + s];
        __syncthreads();
    }
    float inv = 1.f / red[0];

    for (int k = tid; k < len; k += 256) {
        float p = row[k] * inv;
        float h = tf32_rnd(p);
        row[k] = h;
        rlo[k] = p - h;
    }
    for (int k = len + tid; k < LL; k += 256) { row[k] = 0.f; rlo[k] = 0.f; }
}

// ---------------- combine + residual + layernorm (split output) ----------------
__global__ void fuse_ln_kernel(const float* __restrict__ inp,
                               const float* __restrict__ ln_g,
                               const float* __restrict__ ln_b)
{
    int r = blockIdx.x;
    long long base = (long long)r * DD;
    const float* o1 = g_o1 + base;
    const float* o2 = g_o2 + base;
    const float* xr = inp  + base;
    int tid = threadIdx.x;

    __shared__ float ssum[256];
    __shared__ float ssq [256];

    float v[4];
    float s = 0.f, s2 = 0.f;
#pragma unroll
    for (int i = 0; i < 4; i++) {
        int d = tid + i * 256;
        float y = 0.5f * (o1[d] + o2[d]) + xr[d];
        v[i] = y;
        s  += y;
        s2 += y * y;
    }
    ssum[tid] = s;
    ssq [tid] = s2;
    __syncthreads();
    for (int st = 128; st > 0; st >>= 1) {
        if (tid < st) { ssum[tid] += ssum[tid + st]; ssq[tid] += ssq[tid + st]; }
        __syncthreads();
    }
    float mu  = ssum[0] * (1.f / DD);
    float var = ssq[0]  * (1.f / DD) - mu * mu;
    float inv = rsqrtf(var + 1e-5f);
#pragma unroll
    for (int i = 0; i < 4; i++) {
        int d = tid + i * 256;
        float y = (v[i] - mu) * inv * ln_g[d] + ln_b[d];
        float h = tf32_rnd(y);
        g_ynh[base + d] = h;
        g_ynl[base + d] = y - h;
    }
}

// ---------------- host launch ----------------
#define GB(T1, T2, T3, T4, grid, Ah_, Al_, Bh_, Bl_, C_, Cl_, bias_, M_, N_, K_, lda_, ldb_, ldc_, sA_, sB_, sC_) \
    do { \
        tgemm<T1, T2, T3, T4><<<grid, 256, SMEM_DYN>>>(Ah_, Al_, Bh_, Bl_, C_, Cl_, bias_, M_, N_, K_, lda_, ldb_, ldc_, sA_, sB_, sC_); \
        ffgemm<T1, T2, T3, T4><<<grid, 256>>>(Ah_, Al_, Bh_, Bl_, C_, Cl_, bias_, M_, N_, K_, lda_, ldb_, ldc_, sA_, sB_, sC_); \
    } while (0)

extern "C" void kernel_launch(void* const* d_in, const int* in_sizes, int n_in,
                              void* d_out, int out_size)
{
    const float* inputs  = (const float*)d_in[0];
    const float* inputs2 = (const float*)d_in[1];
    const float* Wq      = (const float*)d_in[2];
    const float* Wqu     = (const float*)d_in[3];
    const float* Wk      = (const float*)d_in[4];
    const float* Wv      = (const float*)d_in[5];
    // d_in[6] W_d, d_in[7] h_vec: dead code (A == 0.5 exactly in the reference)
    const float* fc_w    = (const float*)d_in[8];
    const float* fc_b    = (const float*)d_in[9];
    const float* ln_g    = (const float*)d_in[10];
    const float* ln_b    = (const float*)d_in[11];
    float* out = (float*)d_out;

    float *xh, *xl, *xuh, *xul, *qhh, *qhl, *khh, *khl, *quhh, *quhl;
    float *vth, *vtl, *s1, *s1l, *s2, *s2l, *o1, *o2, *ynh, *ynl, *wh, *wl;
    cudaGetSymbolAddress((void**)&xh,   g_xh);
    cudaGetSymbolAddress((void**)&xl,   g_xl);
    cudaGetSymbolAddress((void**)&xuh,  g_xuh);
    cudaGetSymbolAddress((void**)&xul,  g_xul);
    cudaGetSymbolAddress((void**)&qhh,  g_qhh);
    cudaGetSymbolAddress((void**)&qhl,  g_qhl);
    cudaGetSymbolAddress((void**)&khh,  g_khh);
    cudaGetSymbolAddress((void**)&khl,  g_khl);
    cudaGetSymbolAddress((void**)&quhh, g_quhh);
    cudaGetSymbolAddress((void**)&quhl, g_quhl);
    cudaGetSymbolAddress((void**)&vth,  g_vth);
    cudaGetSymbolAddress((void**)&vtl,  g_vtl);
    cudaGetSymbolAddress((void**)&s1,   g_s1);
    cudaGetSymbolAddress((void**)&s1l,  g_s1l);
    cudaGetSymbolAddress((void**)&s2,   g_s2);
    cudaGetSymbolAddress((void**)&s2l,  g_s2l);
    cudaGetSymbolAddress((void**)&o1,   g_o1);
    cudaGetSymbolAddress((void**)&o2,   g_o2);
    cudaGetSymbolAddress((void**)&ynh,  g_ynh);
    cudaGetSymbolAddress((void**)&ynl,  g_ynl);
    cudaGetSymbolAddress((void**)&wh,   g_wh);
    cudaGetSymbolAddress((void**)&wl,   g_wl);

    cudaFuncSetAttribute(tgemm<false, false, false, true >, cudaFuncAttributeMaxDynamicSharedMemorySize, SMEM_DYN);
    cudaFuncSetAttribute(tgemm<true,  false, false, false>, cudaFuncAttributeMaxDynamicSharedMemorySize, SMEM_DYN);
    cudaFuncSetAttribute(tgemm<false, true,  false, false>, cudaFuncAttributeMaxDynamicSharedMemorySize, SMEM_DYN);
    cudaFuncSetAttribute(tgemm<false, false, true,  false>, cudaFuncAttributeMaxDynamicSharedMemorySize, SMEM_DYN);

    const long long sQK = (long long)LL * DD;       // 1,024,000
    const long long sS  = (long long)LL * LL;       // 1,000,000
    const long long sVT = (long long)DD * LL;       // 1,024,000

    // weight hi/lo offsets in packed arrays: [Wq, Wk, Wqu, Wv, fc_w]
    float* wqh = wh + 0LL * DD * DD;  float* wql = wl + 0LL * DD * DD;
    float* wkh = wh + 1LL * DD * DD;  float* wkl = wl + 1LL * DD * DD;
    float* wuh = wh + 2LL * DD * DD;  float* wul = wl + 2LL * DD * DD;
    float* wvh = wh + 3LL * DD * DD;  float* wvl = wl + 3LL * DD * DD;
    float* fch = wh + 4LL * DD * DD;  float* fcl = wl + 4LL * DD * DD;

    // 0. split weights
    int wn = DD * DD;
    wsplit_kernel<<<(wn + 255) / 256, 256>>>(Wq,   wqh, wql, wn);
    wsplit_kernel<<<(wn + 255) / 256, 256>>>(Wk,   wkh, wkl, wn);
    wsplit_kernel<<<(wn + 255) / 256, 256>>>(Wqu,  wuh, wul, wn);
    wsplit_kernel<<<(wn + 255) / 256, 256>>>(Wv,   wvh, wvl, wn);
    wsplit_kernel<<<(wn + 255) / 256, 256>>>(fc_w, fch, fcl, wn);

    // 1. x = inputs + pe, xu = inputs2 + pe (split)
    build_x_kernel<<<(LL * DD + 255) / 256, 256>>>(inputs, inputs2);

    // 2. projections (split outputs)
    dim3 gp(8, 125, 1);
    GB(false, false, false, true, gp, xh,  xl,  wqh, wql, qhh,  qhl,  (const float*)nullptr, MM, DD, DD, DD, DD, DD, 0LL, 0LL, 0LL);
    GB(false, false, false, true, gp, xh,  xl,  wkh, wkl, khh,  khl,  (const float*)nullptr, MM, DD, DD, DD, DD, DD, 0LL, 0LL, 0LL);
    GB(false, false, false, true, gp, xuh, xul, wuh, wul, quhh, quhl, (const float*)nullptr, MM, DD, DD, DD, DD, DD, 0LL, 0LL, 0LL);

    //    Vt = Wv @ x^T per batch : [1024, 1000] (split output)
    dim3 gv(8, 8, NB);
    GB(false, false, false, true, gv, wvh, wvl, xh, xl, vth, vtl, (const float*)nullptr, DD, LL, DD, DD, DD, LL, 0LL, sQK, sVT);

    // 3. scores (causal tile skip): S = Q @ K^T per batch (fp32 out)
    dim3 gs(8, 8, NB);
    GB(true, false, false, false, gs, qhh,  qhl,  khh, khl, s1, s1, (const float*)nullptr, LL, LL, DD, DD, DD, LL, sQK, sQK, sS);
    GB(true, false, false, false, gs, quhh, quhl, khh, khl, s2, s2, (const float*)nullptr, LL, LL, DD, DD, DD, LL, sQK, sQK, sS);

    // 4. causal softmax in place -> (p_hi in s, p_lo separate)
    dim3 gsm(LL, NB);
    softmax_causal_kernel<<<gsm, 256>>>(s1, s1l);
    softmax_causal_kernel<<<gsm, 256>>>(s2, s2l);

    // 5. O = P @ Vt^T per batch (K capped at m0+128 via CKLIM, fp32 out)
    dim3 gpv(8, 8, NB);
    GB(false, true, false, false, gpv, s1, s1l, vth, vtl, o1, o1, (const float*)nullptr, LL, DD, LL, LL, LL, DD, sS, sVT, sQK);
    GB(false, true, false, false, gpv, s2, s2l, vth, vtl, o2, o2, (const float*)nullptr, LL, DD, LL, LL, LL, DD, sS, sVT, sQK);

    // 6. y = 0.5*(o1+o2) + inputs; layernorm -> yn (split)
    fuse_ln_kernel<<<MM, 256>>>(inputs, ln_g, ln_b);

    // 7. out = yn @ fc_w^T + fc_b
    GB(false, false, true, false, gp, ynh, ynl, fch, fcl, out, out, fc_b, MM, DD, DD, DD, DD, DD, 0LL, 0LL, 0LL);
}

// round 5
// speedup vs baseline: 4.4611x; 1.1809x over previous
#include <cuda_runtime.h>
#include <cuda_bf16.h>
#include <cstdint>
#include <math.h>

#define NB 16
#define LL 1000
#define DD 1024
#define MM (NB*LL)   // 16000

typedef __nv_bfloat16 bf16;
typedef __nv_bfloat162 bf162;

// Arch-feature gate: tcgen05 path only in the compute_103a pass; the plain
// compute_103 pass compiles the FFMA fallback. Host launches both (one is a no-op).
#if defined(__CUDA_ARCH__) && (defined(__CUDA_ARCH_FEAT_SM103_ALL) || defined(__CUDA_ARCH_FEAT_SM100_ALL))
#define TC_OK 1
#endif

// ---------------- scratch (static device globals; no allocation) ----------------
// GEMM operands pre-split into bf16 (hi, lo) planes: hi = bf16(v), lo = bf16(v - hi).
__device__ bf16  g_xh  [NB*LL*DD];
__device__ bf16  g_xl  [NB*LL*DD];
__device__ bf16  g_xuh [NB*LL*DD];
__device__ bf16  g_xul [NB*LL*DD];
__device__ bf16  g_qhh [NB*LL*DD];
__device__ bf16  g_qhl [NB*LL*DD];
__device__ bf16  g_khh [NB*LL*DD];
__device__ bf16  g_khl [NB*LL*DD];
__device__ bf16  g_quhh[NB*LL*DD];
__device__ bf16  g_quhl[NB*LL*DD];
__device__ bf16  g_vth [NB*DD*LL];   // V transposed: [batch][1024][1000]
__device__ bf16  g_vtl [NB*DD*LL];
__device__ float g_s1  [NB*LL*LL];   // fp32 scores
__device__ float g_s2  [NB*LL*LL];
__device__ bf16  g_p1h [NB*LL*LL];   // softmax output planes
__device__ bf16  g_p1l [NB*LL*LL];
__device__ bf16  g_p2h [NB*LL*LL];
__device__ bf16  g_p2l [NB*LL*LL];
__device__ float g_o1  [NB*LL*DD];
__device__ float g_o2  [NB*LL*DD];
__device__ bf16  g_ynh [NB*LL*DD];
__device__ bf16  g_ynl [NB*LL*DD];
__device__ bf16  g_wh  [5*DD*DD];    // Wq, Wk, Wqu, Wv, fc_w hi
__device__ bf16  g_wl  [5*DD*DD];    // lo

// ================= helpers =================
__device__ __forceinline__ uint32_t smem_u32(const void* p) {
    uint32_t a;
    asm("{ .reg .u64 t; cvta.to.shared.u64 t, %1; cvt.u32.u64 %0, t; }" : "=r"(a) : "l"(p));
    return a;
}

__device__ __forceinline__ void bsplit(float v, bf16& h, bf16& l) {
    h = __float2bfloat16_rn(v);
    l = __float2bfloat16_rn(v - __bfloat162float(h));
}

#define SWZ(o) ((o) ^ (((o) >> 3) & 0x70))

#ifdef TC_OK
__device__ __forceinline__ bool elect1() {
    uint32_t p;
    asm volatile("{\n\t.reg .pred p;\n\telect.sync _|p, 0xFFFFFFFF;\n\tselp.b32 %0,1,0,p;\n\t}" : "=r"(p));
    return p != 0;
}

#define TC_ALLOC(smaddr, n) \
    asm volatile("tcgen05.alloc.cta_group::1.sync.aligned.shared::cta.b32 [%0], %1;" :: "r"(smaddr), "r"(n) : "memory")
#define TC_RELINQ() \
    asm volatile("tcgen05.relinquish_alloc_permit.cta_group::1.sync.aligned;")
#define TC_DEALLOC(t, n) \
    asm volatile("tcgen05.dealloc.cta_group::1.sync.aligned.b32 %0, %1;" :: "r"(t), "r"(n))
#define TC_COMMIT(mbar) \
    asm volatile("tcgen05.commit.cta_group::1.mbarrier::arrive::one.shared::cluster.b64 [%0];" :: "r"(mbar) : "memory")
#define TC_FENCE_AFTER() \
    asm volatile("tcgen05.fence::after_thread_sync;" ::: "memory")
#define TC_WAIT_LD() \
    asm volatile("tcgen05.wait::ld.sync.aligned;" ::: "memory")
#define FENCE_ASYNC() \
    asm volatile("fence.proxy.async.shared::cta;" ::: "memory")
#define MBAR_INIT(a, c) \
    asm volatile("mbarrier.init.shared.b64 [%0], %1;" :: "r"(a), "r"(c) : "memory")
#define MBAR_INVAL(a) \
    asm volatile("mbarrier.inval.shared.b64 [%0];" :: "r"(a) : "memory")
#define MBWAIT(addr, ph) do { \
    asm volatile("{\n\t.reg .pred P1;\n\tWL%=:\n\t" \
        "mbarrier.try_wait.parity.acquire.cta.shared::cta.b64 P1, [%0], %1, 0x989680;\n\t" \
        "@P1 bra.uni WD%=;\n\tbra.uni WL%=;\n\tWD%=:\n\t}" \
        :: "r"(addr), "r"(ph) : "memory"); } while (0)

#define CP_ASYNC(dst, src, sz) \
    asm volatile("cp.async.cg.shared.global [%0], [%1], 16, %2;" \
        :: "r"(dst), "l"(src), "r"(sz) : "memory")
#define CP_COMMIT() asm volatile("cp.async.commit_group;" ::: "memory")
#define CP_WAIT(n)  asm volatile("cp.async.wait_group %0;" :: "n"(n) : "memory")

__device__ __forceinline__ void mma_bf16(uint32_t d, uint64_t ad, uint64_t bd, uint32_t idesc, uint32_t en) {
    uint32_t z = 0;
    asm volatile("{\n\t.reg .pred p;\n\tsetp.ne.u32 p, %5, 0;\n\t"
                 "tcgen05.mma.cta_group::1.kind::f16 [%0], %1, %2, %3, {%4, %4, %4, %4}, p;\n\t}"
                 :: "r"(d), "l"(ad), "l"(bd), "r"(idesc), "r"(z), "r"(en) : "memory");
}

#define LDTM_X32(r, a) \
    asm volatile("tcgen05.ld.sync.aligned.32x32b.x32.b32 " \
        "{%0, %1, %2, %3, %4, %5, %6, %7, %8, %9, %10, %11, %12, %13, %14, %15, " \
        " %16, %17, %18, %19, %20, %21, %22, %23, %24, %25, %26, %27, %28, %29, %30, %31}, [%32];" \
        : "=r"((r)[0]),  "=r"((r)[1]),  "=r"((r)[2]),  "=r"((r)[3]), \
          "=r"((r)[4]),  "=r"((r)[5]),  "=r"((r)[6]),  "=r"((r)[7]), \
          "=r"((r)[8]),  "=r"((r)[9]),  "=r"((r)[10]), "=r"((r)[11]), \
          "=r"((r)[12]), "=r"((r)[13]), "=r"((r)[14]), "=r"((r)[15]), \
          "=r"((r)[16]), "=r"((r)[17]), "=r"((r)[18]), "=r"((r)[19]), \
          "=r"((r)[20]), "=r"((r)[21]), "=r"((r)[22]), "=r"((r)[23]), \
          "=r"((r)[24]), "=r"((r)[25]), "=r"((r)[26]), "=r"((r)[27]), \
          "=r"((r)[28]), "=r"((r)[29]), "=r"((r)[30]), "=r"((r)[31]) \
        : "r"(a))

// SW128 descriptor: layout=2, version=1, SBO=64, LBO=1 (K-major, 128B rows)
__device__ __forceinline__ uint64_t sdesc(uint32_t addr) {
    const uint64_t base = (uint64_t(2) << 61) | (uint64_t(1) << 46) |
                          (uint64_t(64) << 32) | (uint64_t(1) << 16);
    return base | ((uint64_t)(addr >> 4) & 0x3FFF);
}
#endif // TC_OK

// ================= tcgen05 bf16x2 GEMM, 128x256 tile, cp.async 2-stage =================
// C[M,Nn] = A[M,K] @ B[Nn,K]^T, operands as bf16 (hi, lo) planes, K-major.
// Per K-chunk of 64: Ah/Al 16KB each, Bh/Bl 32KB each => 96KB stage.
#define ST 2
#define STAGE_BYTES 98304
static const int SMEM_DYN = ST * STAGE_BYTES + 1024;

template<bool CSKIP, bool CKLIM, bool BIAS, bool SPLITOUT>
__global__ __launch_bounds__(256, 1)
void tgemm(const bf16* __restrict__ Ah, const bf16* __restrict__ Al,
           const bf16* __restrict__ Bh, const bf16* __restrict__ Bl,
           float* __restrict__ C, bf16* __restrict__ Ch, bf16* __restrict__ Cl,
           const float* __restrict__ bias,
           int M, int Nn, int K, int lda, int ldb, int ldc,
           long long sA, long long sB, long long sC)
{
#ifdef TC_OK
    extern __shared__ char dsm[];
    __shared__ uint32_t s_tmem;
    __shared__ __align__(8) unsigned long long s_mbar[ST];

    int m0 = blockIdx.y * 128, n0 = blockIdx.x * 256;
    if (CSKIP && n0 > m0 + 127) return;

    long long bz = blockIdx.z;
    Ah += bz * sA; Al += bz * sA; Bh += bz * sB; Bl += bz * sB;
    C += bz * sC; Ch += bz * sC; Cl += bz * sC;

    uint32_t sb_raw = smem_u32(dsm);
    uint32_t sbase  = (sb_raw + 1023u) & ~1023u;

    int tid = threadIdx.x;
    int wid = tid >> 5;
    int lid = tid & 31;

    if (wid == 0) { TC_ALLOC(smem_u32(&s_tmem), 256); TC_RELINQ(); }
    if (tid < ST) MBAR_INIT(smem_u32(&s_mbar[tid]), 1);
    __syncthreads();
    uint32_t tmem;
    asm("ld.shared.b32 %0, [%1];" : "=r"(tmem) : "r"(smem_u32(&s_tmem)));

    int kmax = K;
    if (CKLIM && m0 + 128 < kmax) kmax = m0 + 128;
    int nk = (kmax + 63) >> 6;

    // bf16 idesc: dtype=F32, atype=btype=BF16, N=256, M=128
    const uint32_t IDESC = (1u << 4) | (1u << 7) | (1u << 10) | (32u << 17) | (8u << 24);

    // load one K-chunk (64 elems) into its stage; 16B transfers, zero-fill OOB
    auto load_chunk = [&](int c) {
        uint32_t stg = sbase + (uint32_t)(c % ST) * STAGE_BYTES;
        int k0 = c << 6;
        // A planes: 128 rows x 128B each
#pragma unroll
        for (int i = 0; i < 4; i++) {
            int idx = tid + i * 256;         // 0..1023
            int r   = idx >> 3;              // 0..127
            int c8  = idx & 7;               // 16B group
            uint32_t so = SWZ((uint32_t)(r * 128 + c8 * 16));
            int gk = k0 + c8 * 8;
            int gm = m0 + r;
            int sz = (gm < M && gk < K) ? 16 : 0;
            CP_ASYNC(stg + so,          Ah + (long long)gm * lda + gk, sz);
            CP_ASYNC(stg + 16384u + so, Al + (long long)gm * lda + gk, sz);
        }
        // B planes: 256 rows x 128B each
#pragma unroll
        for (int i = 0; i < 8; i++) {
            int idx = tid + i * 256;         // 0..2047
            int r   = idx >> 3;              // 0..255
            int c8  = idx & 7;
            uint32_t so = SWZ((uint32_t)(r * 128 + c8 * 16));
            int gk = k0 + c8 * 8;
            int gn = n0 + r;
            int sz = (gn < Nn && gk < K) ? 16 : 0;
            CP_ASYNC(stg + 32768u + so, Bh + (long long)gn * ldb + gk, sz);
            CP_ASYNC(stg + 65536u + so, Bl + (long long)gn * ldb + gk, sz);
        }
        CP_COMMIT();
    };

    bool mma_thread;
    if (wid == 0) mma_thread = elect1(); else mma_thread = false;

    for (int s = 0; s < ST - 1 && s < nk; s++) load_chunk(s);

    for (int kt = 0; kt < nk; kt++) {
        CP_WAIT(0);                 // ST=2: only chunk kt outstanding here
        FENCE_ASYNC();
        __syncthreads();

        if (mma_thread) {
            uint32_t stg = sbase + (uint32_t)(kt % ST) * STAGE_BYTES;
            uint64_t dah = sdesc(stg);
            uint64_t dal = sdesc(stg + 16384u);
            uint64_t dbh = sdesc(stg + 32768u);
            uint64_t dbl = sdesc(stg + 65536u);
#pragma unroll
            for (int ks = 0; ks < 4; ks++) {   // 4 x K=16 per 64-chunk
                uint32_t en = (kt > 0 || ks > 0) ? 1u : 0u;
                mma_bf16(tmem, dah + ks * 2, dbh + ks * 2, IDESC, en);
                mma_bf16(tmem, dah + ks * 2, dbl + ks * 2, IDESC, 1u);
                mma_bf16(tmem, dal + ks * 2, dbh + ks * 2, IDESC, 1u);
            }
            TC_COMMIT(smem_u32(&s_mbar[kt % ST]));
        }

        int c = kt + ST - 1;
        if (c < nk) {
            if (c >= ST) {
                int m = c / ST;
                MBWAIT(smem_u32(&s_mbar[c % ST]), (m - 1) & 1);
            }
            load_chunk(c);
        }
    }

    if (tid == 0) {
        int m = (nk - 1) / ST;
        MBWAIT(smem_u32(&s_mbar[(nk - 1) % ST]), m & 1);
    }
    __syncthreads();
    TC_FENCE_AFTER();

    // epilogue: warp w -> rows (w&3)*32, cols (w>>2)*128 (+4 x 32-col groups)
    int gm = m0 + (wid & 3) * 32 + lid;
#pragma unroll
    for (int h = 0; h < 4; h++) {
        int cc = (wid >> 2) * 128 + h * 32;
        uint32_t r[32];
        LDTM_X32(r, tmem + cc);
        TC_WAIT_LD();
        if (gm < M) {
#pragma unroll
            for (int c = 0; c < 32; c += 4) {
                int gn = n0 + cc + c;
                if (gn + 4 <= Nn) {
                    float v0 = __uint_as_float(r[c + 0]);
                    float v1 = __uint_as_float(r[c + 1]);
                    float v2 = __uint_as_float(r[c + 2]);
                    float v3 = __uint_as_float(r[c + 3]);
                    if (BIAS) {
                        v0 += bias[gn + 0]; v1 += bias[gn + 1];
                        v2 += bias[gn + 2]; v3 += bias[gn + 3];
                    }
                    if (SPLITOUT) {
                        bf16 h0, l0, h1, l1, h2, l2, h3, l3;
                        bsplit(v0, h0, l0); bsplit(v1, h1, l1);
                        bsplit(v2, h2, l2); bsplit(v3, h3, l3);
                        long long o = (long long)gm * ldc + gn;
                        *(bf162*)(Ch + o)     = bf162(h0, h1);
                        *(bf162*)(Ch + o + 2) = bf162(h2, h3);
                        *(bf162*)(Cl + o)     = bf162(l0, l1);
                        *(bf162*)(Cl + o + 2) = bf162(l2, l3);
                    } else {
                        float4 v = make_float4(v0, v1, v2, v3);
                        *(float4*)(C + (long long)gm * ldc + gn) = v;
                    }
                }
            }
        }
    }

    __syncthreads();
    if (tid < ST) MBAR_INVAL(smem_u32(&s_mbar[tid]));
    if (wid == 0) TC_DEALLOC(tmem, 256);
#endif // TC_OK
}

// ================= FFMA fallback GEMM (plain sm_103 pass only, BN=128) =================
template<bool CSKIP, bool CKLIM, bool BIAS, bool SPLITOUT>
__global__ __launch_bounds__(256, 2)
void ffgemm(const bf16* __restrict__ Ah, const bf16* __restrict__ Al,
            const bf16* __restrict__ Bh, const bf16* __restrict__ Bl,
            float* __restrict__ C, bf16* __restrict__ Ch, bf16* __restrict__ Cl,
            const float* __restrict__ bias,
            int M, int Nn, int K, int lda, int ldb, int ldc,
            long long sA, long long sB, long long sC)
{
#ifndef TC_OK
    const int BM = 128, BN = 128, BK = 16;
    __shared__ float As[BK][BM];
    __shared__ float Bs[BK][BN];

    int bz = blockIdx.z;
    Ah += (long long)bz * sA; Al += (long long)bz * sA;
    Bh += (long long)bz * sB; Bl += (long long)bz * sB;
    C += (long long)bz * sC;  Ch += (long long)bz * sC; Cl += (long long)bz * sC;

    int m0 = blockIdx.y * BM;
    int n0 = blockIdx.x * BN;
    if (CSKIP && n0 > m0 + BM - 1) return;

    int tid  = threadIdx.x;
    int trow = tid >> 4;
    int tcol = tid & 15;

    float acc[8][8];
#pragma unroll
    for (int i = 0; i < 8; i++)
#pragma unroll
        for (int j = 0; j < 8; j++) acc[i][j] = 0.f;

    int ktiles = (K + BK - 1) / BK;
    if (CKLIM) {
        int kl = (m0 + BM + BK - 1) / BK;
        if (kl < ktiles) ktiles = kl;
    }

    for (int kt = 0; kt < ktiles; kt++) {
        int k0 = kt * BK;
#pragma unroll
        for (int jj = 0; jj < 2; jj++) {
            int i  = tid + jj * 256;
            int r  = i >> 2;
            int c4 = (i & 3) * 4;
            float v[4] = {0.f, 0.f, 0.f, 0.f};
            int gr = m0 + r;
            if (gr < M && (k0 + c4 + 4) <= K) {
                const bf16* ph = Ah + (long long)gr * lda + k0 + c4;
                const bf16* pl = Al + (long long)gr * lda + k0 + c4;
                for (int q = 0; q < 4; q++)
                    v[q] = __bfloat162float(ph[q]) + __bfloat162float(pl[q]);
            }
            for (int q = 0; q < 4; q++) As[c4 + q][r] = v[q];
        }
#pragma unroll
        for (int jj = 0; jj < 2; jj++) {
            int i  = tid + jj * 256;
            int r  = i >> 2;
            int c4 = (i & 3) * 4;
            float v[4] = {0.f, 0.f, 0.f, 0.f};
            int gr = n0 + r;
            if (gr < Nn && (k0 + c4 + 4) <= K) {
                const bf16* ph = Bh + (long long)gr * ldb + k0 + c4;
                const bf16* pl = Bl + (long long)gr * ldb + k0 + c4;
                for (int q = 0; q < 4; q++)
                    v[q] = __bfloat162float(ph[q]) + __bfloat162float(pl[q]);
            }
            for (int q = 0; q < 4; q++) Bs[c4 + q][r] = v[q];
        }
        __syncthreads();

#pragma unroll
        for (int kk = 0; kk < BK; kk++) {
            float a[8], b[8];
            *(float4*)&a[0] = *(const float4*)&As[kk][trow * 8];
            *(float4*)&a[4] = *(const float4*)&As[kk][trow * 8 + 4];
            *(float4*)&b[0] = *(const float4*)&Bs[kk][tcol * 8];
            *(float4*)&b[4] = *(const float4*)&Bs[kk][tcol * 8 + 4];
#pragma unroll
            for (int i = 0; i < 8; i++)
#pragma unroll
                for (int j = 0; j < 8; j++)
                    acc[i][j] += a[i] * b[j];
        }
        __syncthreads();
    }

#pragma unroll
    for (int i = 0; i < 8; i++) {
        int gm = m0 + trow * 8 + i;
        if (gm >= M) continue;
#pragma unroll
        for (int j = 0; j < 8; j++) {
            int gn = n0 + tcol * 8 + j;
            if (gn >= Nn) continue;
            float v = acc[i][j];
            if (BIAS) v += bias[gn];
            if (SPLITOUT) {
                bf16 h, l;
                bsplit(v, h, l);
                Ch[(long long)gm * ldc + gn] = h;
                Cl[(long long)gm * ldc + gn] = l;
            } else {
                C[(long long)gm * ldc + gn] = v;
            }
        }
    }
#endif // !TC_OK
}

// ---------------- positional encoding + input add (split bf16 output) ----------------
__global__ void build_x_kernel(const float* __restrict__ inp,
                               const float* __restrict__ inp2)
{
    int idx = blockIdx.x * blockDim.x + threadIdx.x;
    if (idx >= LL * DD) return;
    int l = idx / DD;
    int j = idx % DD;
    float rate = expf(-(float)j * 8.99447363e-3f);
    float ang  = (float)l * rate;
    float pe   = (j & 1) ? cosf(ang) : sinf(ang);
#pragma unroll
    for (int n = 0; n < NB; n++) {
        long long o = (long long)n * LL * DD + idx;
        bf16 h, lo;
        bsplit(inp[o] + pe, h, lo);
        g_xh[o] = h; g_xl[o] = lo;
        bsplit(inp2[o] + pe, h, lo);
        g_xuh[o] = h; g_xul[o] = lo;
    }
}

// ---------------- weight split ----------------
__global__ void wsplit_kernel(const float* __restrict__ src, bf16* __restrict__ hi,
                              bf16* __restrict__ lo, int n)
{
    int i = blockIdx.x * blockDim.x + threadIdx.x;
    if (i >= n) return;
    bf16 h, l;
    bsplit(src[i], h, l);
    hi[i] = h; lo[i] = l;
}

// ---------------- causal softmax: fp32 scores -> bf16 (hi, lo) P planes ----------------
__global__ void softmax_causal_kernel(const float* __restrict__ S,
                                      bf16* __restrict__ Ph, bf16* __restrict__ Pl)
{
    int q = blockIdx.x;
    int n = blockIdx.y;
    long long roff = ((long long)n * LL + q) * (long long)LL;
    const float* row = S + roff;
    bf16* ph = Ph + roff;
    bf16* pl = Pl + roff;
    int len = q + 1;
    int tid = threadIdx.x;
    __shared__ float red[256];

    float mx = -3.4e38f;
    for (int k = tid; k < len; k += 256) mx = fmaxf(mx, row[k]);
    red[tid] = mx;
    __syncthreads();
    for (int s = 128; s > 0; s >>= 1) {
        if (tid < s) red[tid] = fmaxf(red[tid], red[tid + s]);
        __syncthreads();
    }
    mx = red[0];
    __syncthreads();

    float sum = 0.f;
    for (int k = tid; k < len; k += 256) sum += expf(row[k] - mx);
    red[tid] = sum;
    __syncthreads();
    for (int s = 128; s > 0; s >>= 1) {
        if (tid < s) red[tid] += red[tid + s];
        __syncthreads();
    }
    float inv = 1.f / red[0];

    for (int k = tid; k < len; k += 256) {
        float p = expf(row[k] - mx) * inv;
        bf16 h, l;
        bsplit(p, h, l);
        ph[k] = h; pl[k] = l;
    }
    bf16 z = __float2bfloat16_rn(0.f);
    for (int k = len + tid; k < LL; k += 256) { ph[k] = z; pl[k] = z; }
}

// ---------------- combine + residual + layernorm (split bf16 output) ----------------
__global__ void fuse_ln_kernel(const float* __restrict__ inp,
                               const float* __restrict__ ln_g,
                               const float* __restrict__ ln_b)
{
    int r = blockIdx.x;
    long long base = (long long)r * DD;
    const float* o1 = g_o1 + base;
    const float* o2 = g_o2 + base;
    const float* xr = inp  + base;
    int tid = threadIdx.x;

    __shared__ float ssum[256];
    __shared__ float ssq [256];

    float v[4];
    float s = 0.f, s2 = 0.f;
#pragma unroll
    for (int i = 0; i < 4; i++) {
        int d = tid + i * 256;
        float y = 0.5f * (o1[d] + o2[d]) + xr[d];
        v[i] = y;
        s  += y;
        s2 += y * y;
    }
    ssum[tid] = s;
    ssq [tid] = s2;
    __syncthreads();
    for (int st = 128; st > 0; st >>= 1) {
        if (tid < st) { ssum[tid] += ssum[tid + st]; ssq[tid] += ssq[tid + st]; }
        __syncthreads();
    }
    float mu  = ssum[0] * (1.f / DD);
    float var = ssq[0]  * (1.f / DD) - mu * mu;
    float inv = rsqrtf(var + 1e-5f);
#pragma unroll
    for (int i = 0; i < 4; i++) {
        int d = tid + i * 256;
        float y = (v[i] - mu) * inv * ln_g[d] + ln_b[d];
        bf16 h, l;
        bsplit(y, h, l);
        g_ynh[base + d] = h;
        g_ynl[base + d] = l;
    }
}

// ---------------- host launch ----------------
#define GB(T1, T2, T3, T4, gt, gf, Ah_, Al_, Bh_, Bl_, C_, Ch_, Cl_, bias_, M_, N_, K_, lda_, ldb_, ldc_, sA_, sB_, sC_) \
    do { \
        tgemm<T1, T2, T3, T4><<<gt, 256, SMEM_DYN>>>(Ah_, Al_, Bh_, Bl_, C_, Ch_, Cl_, bias_, M_, N_, K_, lda_, ldb_, ldc_, sA_, sB_, sC_); \
        ffgemm<T1, T2, T3, T4><<<gf, 256>>>(Ah_, Al_, Bh_, Bl_, C_, Ch_, Cl_, bias_, M_, N_, K_, lda_, ldb_, ldc_, sA_, sB_, sC_); \
    } while (0)

extern "C" void kernel_launch(void* const* d_in, const int* in_sizes, int n_in,
                              void* d_out, int out_size)
{
    const float* inputs  = (const float*)d_in[0];
    const float* inputs2 = (const float*)d_in[1];
    const float* Wq      = (const float*)d_in[2];
    const float* Wqu     = (const float*)d_in[3];
    const float* Wk      = (const float*)d_in[4];
    const float* Wv      = (const float*)d_in[5];
    // d_in[6] W_d, d_in[7] h_vec: dead code (A == 0.5 exactly in the reference)
    const float* fc_w    = (const float*)d_in[8];
    const float* fc_b    = (const float*)d_in[9];
    const float* ln_g    = (const float*)d_in[10];
    const float* ln_b    = (const float*)d_in[11];
    float* out = (float*)d_out;

    bf16 *xh, *xl, *xuh, *xul, *qhh, *qhl, *khh, *khl, *quhh, *quhl;
    bf16 *vth, *vtl, *p1h, *p1l, *p2h, *p2l, *ynh, *ynl, *wh, *wl;
    float *s1, *s2, *o1, *o2;
    cudaGetSymbolAddress((void**)&xh,   g_xh);
    cudaGetSymbolAddress((void**)&xl,   g_xl);
    cudaGetSymbolAddress((void**)&xuh,  g_xuh);
    cudaGetSymbolAddress((void**)&xul,  g_xul);
    cudaGetSymbolAddress((void**)&qhh,  g_qhh);
    cudaGetSymbolAddress((void**)&qhl,  g_qhl);
    cudaGetSymbolAddress((void**)&khh,  g_khh);
    cudaGetSymbolAddress((void**)&khl,  g_khl);
    cudaGetSymbolAddress((void**)&quhh, g_quhh);
    cudaGetSymbolAddress((void**)&quhl, g_quhl);
    cudaGetSymbolAddress((void**)&vth,  g_vth);
    cudaGetSymbolAddress((void**)&vtl,  g_vtl);
    cudaGetSymbolAddress((void**)&s1,   g_s1);
    cudaGetSymbolAddress((void**)&s2,   g_s2);
    cudaGetSymbolAddress((void**)&p1h,  g_p1h);
    cudaGetSymbolAddress((void**)&p1l,  g_p1l);
    cudaGetSymbolAddress((void**)&p2h,  g_p2h);
    cudaGetSymbolAddress((void**)&p2l,  g_p2l);
    cudaGetSymbolAddress((void**)&o1,   g_o1);
    cudaGetSymbolAddress((void**)&o2,   g_o2);
    cudaGetSymbolAddress((void**)&ynh,  g_ynh);
    cudaGetSymbolAddress((void**)&ynl,  g_ynl);
    cudaGetSymbolAddress((void**)&wh,   g_wh);
    cudaGetSymbolAddress((void**)&wl,   g_wl);

    cudaFuncSetAttribute(tgemm<false, false, false, true >, cudaFuncAttributeMaxDynamicSharedMemorySize, SMEM_DYN);
    cudaFuncSetAttribute(tgemm<true,  false, false, false>, cudaFuncAttributeMaxDynamicSharedMemorySize, SMEM_DYN);
    cudaFuncSetAttribute(tgemm<false, true,  false, false>, cudaFuncAttributeMaxDynamicSharedMemorySize, SMEM_DYN);
    cudaFuncSetAttribute(tgemm<false, false, true,  false>, cudaFuncAttributeMaxDynamicSharedMemorySize, SMEM_DYN);

    const long long sQK = (long long)LL * DD;       // 1,024,000
    const long long sS  = (long long)LL * LL;       // 1,000,000
    const long long sVT = (long long)DD * LL;       // 1,024,000

    bf16* wqh = wh + 0LL * DD * DD;  bf16* wql = wl + 0LL * DD * DD;
    bf16* wkh = wh + 1LL * DD * DD;  bf16* wkl = wl + 1LL * DD * DD;
    bf16* wuh = wh + 2LL * DD * DD;  bf16* wul = wl + 2LL * DD * DD;
    bf16* wvh = wh + 3LL * DD * DD;  bf16* wvl = wl + 3LL * DD * DD;
    bf16* fch = wh + 4LL * DD * DD;  bf16* fcl = wl + 4LL * DD * DD;

    // 0. split weights
    int wn = DD * DD;
    wsplit_kernel<<<(wn + 255) / 256, 256>>>(Wq,   wqh, wql, wn);
    wsplit_kernel<<<(wn + 255) / 256, 256>>>(Wk,   wkh, wkl, wn);
    wsplit_kernel<<<(wn + 255) / 256, 256>>>(Wqu,  wuh, wul, wn);
    wsplit_kernel<<<(wn + 255) / 256, 256>>>(Wv,   wvh, wvl, wn);
    wsplit_kernel<<<(wn + 255) / 256, 256>>>(fc_w, fch, fcl, wn);

    // 1. x = inputs + pe, xu = inputs2 + pe (split)
    build_x_kernel<<<(LL * DD + 255) / 256, 256>>>(inputs, inputs2);

    // 2. projections (split bf16 outputs)
    dim3 gpT(4, 125, 1), gpF(8, 125, 1);
    GB(false, false, false, true, gpT, gpF, xh,  xl,  wqh, wql, (float*)nullptr, qhh,  qhl,  (const float*)nullptr, MM, DD, DD, DD, DD, DD, 0LL, 0LL, 0LL);
    GB(false, false, false, true, gpT, gpF, xh,  xl,  wkh, wkl, (float*)nullptr, khh,  khl,  (const float*)nullptr, MM, DD, DD, DD, DD, DD, 0LL, 0LL, 0LL);
    GB(false, false, false, true, gpT, gpF, xuh, xul, wuh, wul, (float*)nullptr, quhh, quhl, (const float*)nullptr, MM, DD, DD, DD, DD, DD, 0LL, 0LL, 0LL);

    //    Vt = Wv @ x^T per batch : [1024, 1000] (split bf16 output)
    dim3 gvT(4, 8, NB), gvF(8, 8, NB);
    GB(false, false, false, true, gvT, gvF, wvh, wvl, xh, xl, (float*)nullptr, vth, vtl, (const float*)nullptr, DD, LL, DD, DD, DD, LL, 0LL, sQK, sVT);

    // 3. scores (causal tile skip): S = Q @ K^T per batch (fp32 out)
    dim3 gsT(4, 8, NB), gsF(8, 8, NB);
    GB(true, false, false, false, gsT, gsF, qhh,  qhl,  khh, khl, s1, (bf16*)nullptr, (bf16*)nullptr, (const float*)nullptr, LL, LL, DD, DD, DD, LL, sQK, sQK, sS);
    GB(true, false, false, false, gsT, gsF, quhh, quhl, khh, khl, s2, (bf16*)nullptr, (bf16*)nullptr, (const float*)nullptr, LL, LL, DD, DD, DD, LL, sQK, sQK, sS);

    // 4. causal softmax -> bf16 P planes
    dim3 gsm(LL, NB);
    softmax_causal_kernel<<<gsm, 256>>>(s1, p1h, p1l);
    softmax_causal_kernel<<<gsm, 256>>>(s2, p2h, p2l);

    // 5. O = P @ Vt^T per batch (K capped at m0+128 via CKLIM, fp32 out)
    dim3 gvpT(4, 8, NB), gvpF(8, 8, NB);
    GB(false, true, false, false, gvpT, gvpF, p1h, p1l, vth, vtl, o1, (bf16*)nullptr, (bf16*)nullptr, (const float*)nullptr, LL, DD, LL, LL, LL, DD, sS, sVT, sQK);
    GB(false, true, false, false, gvpT, gvpF, p2h, p2l, vth, vtl, o2, (bf16*)nullptr, (bf16*)nullptr, (const float*)nullptr, LL, DD, LL, LL, LL, DD, sS, sVT, sQK);

    // 6. y = 0.5*(o1+o2) + inputs; layernorm -> yn (split)
    fuse_ln_kernel<<<MM, 256>>>(inputs, ln_g, ln_b);

    // 7. out = yn @ fc_w^T + fc_b
    GB(false, false, true, false, gpT, gpF, ynh, ynl, fch, fcl, out, (bf16*)nullptr, (bf16*)nullptr, fc_b, MM, DD, DD, DD, DD, DD, 0LL, 0LL, 0LL);
}